// round 14
// baseline (speedup 1.0000x reference)
#include <cuda_runtime.h>
#include <cuda_bf16.h>
#include <cstdint>
#include <cstddef>

// Problem constants
#define B_  16
#define U_  512
#define L_  1024
#define H_  8
#define D_  64
#define SCALE_ 0.125f   // 1/sqrt(64)

// Scratch (device globals — allocation-free rule).
__device__ __align__(256) float g_Q[(size_t)B_ * U_ * L_];
__device__ __align__(256) float g_K[(size_t)B_ * U_ * L_];
__device__ __align__(256) float g_C[(size_t)B_ * U_ * L_];

// ===========================================================================
// Arch gating
// ===========================================================================
#if defined(__CUDA_ARCH_FEAT_SM103_ALL) || defined(__CUDA_ARCH_FEAT_SM100_ALL) || \
    defined(__CUDA_ARCH_FAMILY_SPECIFIC__) || defined(__CUDA_ARCH_SPECIFIC__)
#define TC_OK 1
#else
#define TC_OK 0
#endif

__device__ __forceinline__ uint32_t smem_to_u32(const void* p) {
    uint32_t a;
    asm("{ .reg .u64 t; cvta.to.shared.u64 t, %1; cvt.u32.u64 %0, t; }" : "=r"(a) : "l"(p));
    return a;
}
#define MBARRIER_INIT(mbar, count) \
    asm volatile("mbarrier.init.shared.b64 [%0], %1;" \
                 :: "r"((uint32_t)(mbar)), "r"((uint32_t)(count)) : "memory")
#define MBARRIER_WAIT_PARITY(mbar, parity) do {                                   \
    uint32_t _m = (uint32_t)(mbar); uint32_t _p = (uint32_t)(parity);             \
    asm volatile("{\n\t.reg .pred P1;\n\t"                                        \
        "WAIT_LOOP_%=:\n\t"                                                        \
        "mbarrier.try_wait.parity.acquire.cta.shared::cta.b64 P1, [%0], %1, 0x989680;\n\t" \
        "@P1 bra.uni WAIT_DONE_%=;\n\t"                                            \
        "bra.uni WAIT_LOOP_%=;\n\t"                                                \
        "WAIT_DONE_%=:\n\t}" :: "r"(_m), "r"(_p) : "memory");                      \
} while (0)
#define FENCE_PROXY_ASYNC_SHARED_CTA() asm volatile("fence.proxy.async.shared::cta;" ::: "memory")

#if TC_OK
__device__ __forceinline__ uint32_t elect_one_pred() {
    uint32_t pred;
    asm volatile("{\n\t.reg .pred p;\n\telect.sync _|p, 0xFFFFFFFF;\n\tselp.b32 %0, 1, 0, p;\n\t}"
                 : "=r"(pred));
    return pred;
}
#define TCGEN05_ALLOC(smem_result_addr, nCols) \
    asm volatile("tcgen05.alloc.cta_group::1.sync.aligned.shared::cta.b32 [%0], %1;" \
                 :: "r"((uint32_t)(smem_result_addr)), "r"((uint32_t)(nCols)) : "memory")
#define TCGEN05_DEALLOC(tmem_addr, nCols) \
    asm volatile("tcgen05.dealloc.cta_group::1.sync.aligned.b32 %0, %1;" \
                 :: "r"(tmem_addr), "r"((uint32_t)(nCols)))
#define TCGEN05_RELINQUISH() \
    asm volatile("tcgen05.relinquish_alloc_permit.cta_group::1.sync.aligned;")
#define TCGEN05_COMMIT(mbar) \
    asm volatile("tcgen05.commit.cta_group::1.mbarrier::arrive::one.shared::cluster.b64 [%0];" \
                 :: "r"((uint32_t)(mbar)) : "memory")
#define TCGEN05_FENCE_BEFORE() asm volatile("tcgen05.fence::before_thread_sync;" ::: "memory")
#define TCGEN05_FENCE_AFTER()  asm volatile("tcgen05.fence::after_thread_sync;"  ::: "memory")
#define TCGEN05_WAIT_LD()      asm volatile("tcgen05.wait::ld.sync.aligned;"     ::: "memory")
#define TCGEN05_LD_32X32B_X32(r, tmem_addr) \
    asm volatile( \
        "tcgen05.ld.sync.aligned.32x32b.x32.b32 " \
        "{%0, %1, %2, %3, %4, %5, %6, %7, " \
        " %8, %9, %10, %11, %12, %13, %14, %15, " \
        " %16, %17, %18, %19, %20, %21, %22, %23, " \
        " %24, %25, %26, %27, %28, %29, %30, %31}, [%32];" \
        : "=r"((r)[0]),  "=r"((r)[1]),  "=r"((r)[2]),  "=r"((r)[3]), \
          "=r"((r)[4]),  "=r"((r)[5]),  "=r"((r)[6]),  "=r"((r)[7]), \
          "=r"((r)[8]),  "=r"((r)[9]),  "=r"((r)[10]), "=r"((r)[11]), \
          "=r"((r)[12]), "=r"((r)[13]), "=r"((r)[14]), "=r"((r)[15]), \
          "=r"((r)[16]), "=r"((r)[17]), "=r"((r)[18]), "=r"((r)[19]), \
          "=r"((r)[20]), "=r"((r)[21]), "=r"((r)[22]), "=r"((r)[23]), \
          "=r"((r)[24]), "=r"((r)[25]), "=r"((r)[26]), "=r"((r)[27]), \
          "=r"((r)[28]), "=r"((r)[29]), "=r"((r)[30]), "=r"((r)[31]) \
        : "r"(tmem_addr))
#define TCGEN05_LD_32X32B_X16(r, tmem_addr) \
    asm volatile( \
        "tcgen05.ld.sync.aligned.32x32b.x16.b32 " \
        "{%0, %1, %2, %3, %4, %5, %6, %7, " \
        " %8, %9, %10, %11, %12, %13, %14, %15}, [%16];" \
        : "=r"((r)[0]),  "=r"((r)[1]),  "=r"((r)[2]),  "=r"((r)[3]), \
          "=r"((r)[4]),  "=r"((r)[5]),  "=r"((r)[6]),  "=r"((r)[7]), \
          "=r"((r)[8]),  "=r"((r)[9]),  "=r"((r)[10]), "=r"((r)[11]), \
          "=r"((r)[12]), "=r"((r)[13]), "=r"((r)[14]), "=r"((r)[15]) \
        : "r"(tmem_addr))

__device__ __forceinline__ void mma_f16_ss(uint32_t d_tmem, uint64_t a_desc,
                                           uint64_t b_desc, uint32_t idesc,
                                           uint32_t enable) {
    asm volatile(
        "{\n\t"
        ".reg .pred p;\n\t"
        "setp.ne.u32 p, %5, 0;\n\t"
        "tcgen05.mma.cta_group::1.kind::f16 [%0], %1, %2, %3, {%4, %4, %4, %4}, p;\n\t"
        "}"
        :: "r"(d_tmem), "l"(a_desc), "l"(b_desc), "r"(idesc), "r"(0u), "r"(enable)
        : "memory");
}
#endif  // TC_OK

// K-major SW128 descriptor
__device__ __forceinline__ uint64_t desc_k_major(uint32_t addr) {
    return ((uint64_t)(addr >> 4) & 0x3FFF)
         | (1ull << 16) | (64ull << 32) | (1ull << 46) | (2ull << 61);
}

#define SW128(off) ((off) ^ (((off) >> 3) & 0x70))

#define IDESC_BF16_N128 0x8200490u
#define IDESC_BF16_N64  0x8100490u

__device__ __forceinline__ void bf16_split(float x, uint16_t& hi, uint16_t& lo) {
    __nv_bfloat16 h = __float2bfloat16(x);
    float r = x - __bfloat162float(h);
    __nv_bfloat16 l = __float2bfloat16(r);
    hi = __bfloat16_as_ushort(h);
    lo = __bfloat16_as_ushort(l);
}

// ===========================================================================
// tcgen05 split-bf16 channel-mix GEMM (R12 proven, unchanged).
// ===========================================================================
#define TCG_SMEM_BYTES 66688

template <bool FUSE>
__global__ __launch_bounds__(256, 2) __cluster_dims__(1, 1, 1) void tc_gemm(
    const float* __restrict__ Wa, const float* __restrict__ Xa,
    const float* __restrict__ Wb, const float* __restrict__ Xb,
    const float* __restrict__ X2, float* __restrict__ OutA,
    float* __restrict__ OutB)
{
#if TC_OK
    extern __shared__ uint8_t dsm[];
    const uint32_t raw  = smem_to_u32(dsm);
    const uint32_t base = (raw + 1023u) & ~1023u;
    uint8_t* p = dsm + (base - raw);

    const uint32_t ctrl = base + 65536;
    const uint32_t mbar = ctrl + 8;

    const float* W; const float* X1; float* Out; int b;
    if (blockIdx.z < B_) { W = Wa; X1 = Xa; Out = OutA; b = blockIdx.z; }
    else                 { W = Wb; X1 = Xb; Out = OutB; b = blockIdx.z - B_; }

    const int row0 = blockIdx.y * 128;
    const int col0 = blockIdx.x * 128;
    const int tid  = threadIdx.x;
    const int wid  = tid >> 5;
    const int lid  = tid & 31;

    if (wid == 0) {
        TCGEN05_ALLOC(ctrl, 256);
        TCGEN05_RELINQUISH();
    }
    if (tid == 0) MBARRIER_INIT(mbar, 1);
    __syncthreads();
    uint32_t tmem;
    asm volatile("ld.shared.b32 %0, [%1];" : "=r"(tmem) : "r"(ctrl));

    const float* Wb_  = W + (size_t)row0 * U_;
    const float* X1b = X1 + (size_t)b * U_ * L_ + col0;
    const float* X2b = FUSE ? (X2 + (size_t)b * U_ * L_ + col0) : nullptr;

    float4 aR[8];
    float  bR[4][8];

    auto load_regs = [&](int c) {
        const int k0 = c * 64;
#pragma unroll
        for (int t = 0; t < 8; t++) {
            int idx = tid + t * 256;
            int m  = idx >> 4;
            int k4 = (idx & 15) << 2;
            aR[t] = *(const float4*)(Wb_ + (size_t)m * U_ + k0 + k4);
        }
#pragma unroll
        for (int ei = 0; ei < 4; ei++) {
            int n = lid + 32 * ei;
#pragma unroll
            for (int kk = 0; kk < 8; kk++) {
                size_t ro = (size_t)(k0 + wid * 8 + kk) * L_ + n;
                float v = X1b[ro];
                if (FUSE) v = 0.5f * (v + X2b[ro]);
                bR[ei][kk] = v;
            }
        }
    };

    auto store_stage = [&]() {
#pragma unroll
        for (int t = 0; t < 8; t++) {
            int idx = tid + t * 256;
            int m  = idx >> 4;
            int k4 = (idx & 15) << 2;
            float4 v = aR[t];
            uint16_t h0, l0, h1, l1, h2, l2, h3, l3;
            bf16_split(v.x, h0, l0); bf16_split(v.y, h1, l1);
            bf16_split(v.z, h2, l2); bf16_split(v.w, h3, l3);
            uint2 hv = make_uint2((uint32_t)h0 | ((uint32_t)h1 << 16),
                                  (uint32_t)h2 | ((uint32_t)h3 << 16));
            uint2 lv = make_uint2((uint32_t)l0 | ((uint32_t)l1 << 16),
                                  (uint32_t)l2 | ((uint32_t)l3 << 16));
            uint32_t off = (uint32_t)((m >> 3) * 1024 + (m & 7) * 128 + k4 * 2);
            uint32_t sw = SW128(off);
            *(uint2*)(p + sw)         = hv;
            *(uint2*)(p + 16384 + sw) = lv;
        }
#pragma unroll
        for (int ei = 0; ei < 4; ei++) {
            int n = lid + 32 * ei;
            uint16_t h[8], l[8];
#pragma unroll
            for (int kk = 0; kk < 8; kk++) bf16_split(bR[ei][kk], h[kk], l[kk]);
            uint4 hv = make_uint4((uint32_t)h[0] | ((uint32_t)h[1] << 16),
                                  (uint32_t)h[2] | ((uint32_t)h[3] << 16),
                                  (uint32_t)h[4] | ((uint32_t)h[5] << 16),
                                  (uint32_t)h[6] | ((uint32_t)h[7] << 16));
            uint4 lv = make_uint4((uint32_t)l[0] | ((uint32_t)l[1] << 16),
                                  (uint32_t)l[2] | ((uint32_t)l[3] << 16),
                                  (uint32_t)l[4] | ((uint32_t)l[5] << 16),
                                  (uint32_t)l[6] | ((uint32_t)l[7] << 16));
            uint32_t off = (uint32_t)((n >> 3) * 1024 + (n & 7) * 128 + wid * 16);
            uint32_t sw = SW128(off);
            *(uint4*)(p + 32768 + sw) = hv;
            *(uint4*)(p + 49152 + sw) = lv;
        }
        FENCE_PROXY_ASYNC_SHARED_CTA();
    };

    load_regs(0);
    store_stage();
    __syncthreads();

    const int NC = U_ / 64;   // 8 chunks
    for (int c = 0; c < NC; c++) {
        if (wid == 0 && elect_one_pred()) {
            uint64_t ahi = desc_k_major(base);
            uint64_t alo = desc_k_major(base + 16384);
            uint64_t bhi = desc_k_major(base + 32768);
            uint64_t blo = desc_k_major(base + 49152);
#pragma unroll
            for (int s = 0; s < 4; s++) {
                uint64_t so = (uint64_t)(s * 2);
                mma_f16_ss(tmem, ahi + so, bhi + so, IDESC_BF16_N128,
                           (c == 0 && s == 0) ? 0u : 1u);
                mma_f16_ss(tmem, ahi + so, blo + so, IDESC_BF16_N128, 1u);
                mma_f16_ss(tmem, alo + so, bhi + so, IDESC_BF16_N128, 1u);
            }
            TCGEN05_COMMIT(mbar);
        }
        if (c + 1 < NC) load_regs(c + 1);
        MBARRIER_WAIT_PARITY(mbar, c & 1);
        if (c + 1 < NC) {
            store_stage();
            __syncthreads();
        }
    }

    TCGEN05_FENCE_AFTER();

    if (wid < 4) {
        const int m = wid * 32 + lid;
        float* op = Out + ((size_t)b * U_ + row0 + m) * L_ + col0;
#pragma unroll
        for (int j = 0; j < 4; j++) {
            uint32_t r32[32];
            TCGEN05_LD_32X32B_X32(r32, tmem + j * 32);
            TCGEN05_WAIT_LD();
            TCGEN05_FENCE_BEFORE();
#pragma unroll
            for (int q = 0; q < 8; q++) {
                float4 v = make_float4(__uint_as_float(r32[q * 4 + 0]),
                                       __uint_as_float(r32[q * 4 + 1]),
                                       __uint_as_float(r32[q * 4 + 2]),
                                       __uint_as_float(r32[q * 4 + 3]));
                *(float4*)(op + j * 32 + q * 4) = v;
            }
        }
    }
    __syncthreads();
    if (wid == 0) TCGEN05_DEALLOC(tmem, 256);
#else
    (void)Wa; (void)Xa; (void)Wb; (void)Xb; (void)X2; (void)OutA; (void)OutB;
#endif
}

// ===========================================================================
// tcgen05 attention — single-sync pipelined loop; mask prefetched + packed
// to a 1-reg bitmask during the MMA window; single LDTM x32 per iteration.
// smem: QHI 0 | QLO 16384 | KTHI 32768 | KTLO 40960 | KHI 49152 | KLO 57344
//       SHI 65536 | SLO 81920 | ctrl 98304 | cnts 98336
// ===========================================================================
#define AT_SMEM_BYTES 100384

__global__ __launch_bounds__(256, 2) __cluster_dims__(1, 1, 1) void attn_tc(
    const float* __restrict__ Q, const float* __restrict__ K,
    const int* __restrict__ mask, float* __restrict__ C)
{
#if TC_OK
    extern __shared__ uint8_t dsm[];
    const uint32_t raw  = smem_to_u32(dsm);
    const uint32_t base = (raw + 1023u) & ~1023u;
    uint8_t* p = dsm + (base - raw);

    const uint32_t QHI = base, QLO = base + 16384;
    const uint32_t KTHI = base + 32768, KTLO = base + 40960;
    const uint32_t KHI = base + 49152, KLO = base + 57344;
    const uint32_t SHI = base + 65536, SLO = base + 81920;
    const uint32_t ctrl = base + 98304;
    const uint32_t m1 = ctrl + 8;
    const uint32_t m2 = ctrl + 16;
    int* cnts = (int*)(p + 98336);

    const int b  = blockIdx.z;
    const int h  = blockIdx.x;
    const int x0 = blockIdx.y * 128;
    const int tid = threadIdx.x;
    const int wid = tid >> 5;
    const int lid = tid & 31;
    const int sub  = wid & 3;
    const int half = wid >> 2;

    if (wid == 0) {
        TCGEN05_ALLOC(ctrl, 256);
        TCGEN05_RELINQUISH();
    }
    if (tid == 0) { MBARRIER_INIT(m1, 1); MBARRIER_INIT(m2, 1); }
    __syncthreads();
    uint32_t tmem;
    asm volatile("ld.shared.b32 %0, [%1];" : "=r"(tmem) : "r"(ctrl));

    const float* Qb = Q + ((size_t)(b * U_ + h * D_)) * L_ + x0;
    const float* Kb = K + ((size_t)(b * U_ + h * D_)) * L_;
    const int*   Mb = mask + ((size_t)b * L_ + x0) * L_;

    const int x = sub * 32 + lid;

    // ---- stage Q^T [128x][64d] hi/lo (scale folded), once ----
#pragma unroll
    for (int ei = 0; ei < 4; ei++) {
        int xq = lid + 32 * ei;
        float rv[8];
#pragma unroll
        for (int kk = 0; kk < 8; kk++)
            rv[kk] = Qb[(size_t)(wid * 8 + kk) * L_ + xq] * SCALE_;
        uint16_t hh[8], ll[8];
#pragma unroll
        for (int kk = 0; kk < 8; kk++) bf16_split(rv[kk], hh[kk], ll[kk]);
        uint4 hv = make_uint4((uint32_t)hh[0] | ((uint32_t)hh[1] << 16),
                              (uint32_t)hh[2] | ((uint32_t)hh[3] << 16),
                              (uint32_t)hh[4] | ((uint32_t)hh[5] << 16),
                              (uint32_t)hh[6] | ((uint32_t)hh[7] << 16));
        uint4 lv = make_uint4((uint32_t)ll[0] | ((uint32_t)ll[1] << 16),
                              (uint32_t)ll[2] | ((uint32_t)ll[3] << 16),
                              (uint32_t)ll[4] | ((uint32_t)ll[5] << 16),
                              (uint32_t)ll[6] | ((uint32_t)ll[7] << 16));
        uint32_t sw = SW128((uint32_t)((xq >> 3) * 1024 + (xq & 7) * 128 + wid * 16));
        *(uint4*)(p + (QHI - base) + sw) = hv;
        *(uint4*)(p + (QLO - base) + sw) = lv;
    }

    // reg prefetch state
    float  ktR[2][8];
    float4 kR[4];

    auto load_kt_regs = [&](int y0n) {
#pragma unroll
        for (int ei = 0; ei < 2; ei++) {
            int y = lid + 32 * ei;
#pragma unroll
            for (int kk = 0; kk < 8; kk++)
                ktR[ei][kk] = Kb[(size_t)(wid * 8 + kk) * L_ + y0n + y];
        }
    };
    auto load_k_regs = [&](int y0n) {
#pragma unroll
        for (int t = 0; t < 4; t++) {
            int idx = tid + t * 256;
            int d  = idx >> 4;
            int y4 = (idx & 15) << 2;
            kR[t] = *(const float4*)(Kb + (size_t)d * L_ + y0n + y4);
        }
    };
    // mask bitmask for this thread's 32 y-columns of tile y0n
    auto load_mask_bits = [&](int y0n) -> uint32_t {
        const int* mrow = Mb + (size_t)x * L_ + y0n + half * 32;
        uint32_t bits = 0;
#pragma unroll
        for (int t = 0; t < 8; t++) {
            int4 m = *(const int4*)(mrow + t * 4);
            bits |= (m.x != 0 ? 1u : 0u) << (t * 4 + 0);
            bits |= (m.y != 0 ? 1u : 0u) << (t * 4 + 1);
            bits |= (m.z != 0 ? 1u : 0u) << (t * 4 + 2);
            bits |= (m.w != 0 ? 1u : 0u) << (t * 4 + 3);
        }
        return bits;
    };
    auto store_kt = [&]() {
#pragma unroll
        for (int ei = 0; ei < 2; ei++) {
            int y = lid + 32 * ei;
            uint16_t hh[8], ll[8];
#pragma unroll
            for (int kk = 0; kk < 8; kk++) bf16_split(ktR[ei][kk], hh[kk], ll[kk]);
            uint4 hv = make_uint4((uint32_t)hh[0] | ((uint32_t)hh[1] << 16),
                                  (uint32_t)hh[2] | ((uint32_t)hh[3] << 16),
                                  (uint32_t)hh[4] | ((uint32_t)hh[5] << 16),
                                  (uint32_t)hh[6] | ((uint32_t)hh[7] << 16));
            uint4 lv = make_uint4((uint32_t)ll[0] | ((uint32_t)ll[1] << 16),
                                  (uint32_t)ll[2] | ((uint32_t)ll[3] << 16),
                                  (uint32_t)ll[4] | ((uint32_t)ll[5] << 16),
                                  (uint32_t)ll[6] | ((uint32_t)ll[7] << 16));
            uint32_t sw = SW128((uint32_t)((y >> 3) * 1024 + (y & 7) * 128 + wid * 16));
            *(uint4*)(p + (KTHI - base) + sw) = hv;
            *(uint4*)(p + (KTLO - base) + sw) = lv;
        }
    };
    auto store_k = [&]() {
#pragma unroll
        for (int t = 0; t < 4; t++) {
            int idx = tid + t * 256;
            int d  = idx >> 4;
            int y4 = (idx & 15) << 2;
            float4 v = kR[t];
            uint16_t h0, l0, h1, l1, h2, l2, h3, l3;
            bf16_split(v.x, h0, l0); bf16_split(v.y, h1, l1);
            bf16_split(v.z, h2, l2); bf16_split(v.w, h3, l3);
            uint2 hv = make_uint2((uint32_t)h0 | ((uint32_t)h1 << 16),
                                  (uint32_t)h2 | ((uint32_t)h3 << 16));
            uint2 lv = make_uint2((uint32_t)l0 | ((uint32_t)l1 << 16),
                                  (uint32_t)l2 | ((uint32_t)l3 << 16));
            uint32_t sw = SW128((uint32_t)((d >> 3) * 1024 + (d & 7) * 128 + y4 * 2));
            *(uint2*)(p + (KHI - base) + sw) = hv;
            *(uint2*)(p + (KLO - base) + sw) = lv;
        }
    };

    // prologue: stage KT(0), issue MMA1(0); prefetch KT(1), K(0), mask(0)
    load_kt_regs(0);
    store_kt();
    FENCE_PROXY_ASYNC_SHARED_CTA();
    __syncthreads();
    if (wid == 0 && elect_one_pred()) {
        uint64_t ah = desc_k_major(QHI), al = desc_k_major(QLO);
        uint64_t bh = desc_k_major(KTHI), bl = desc_k_major(KTLO);
#pragma unroll
        for (int s = 0; s < 4; s++) {
            uint64_t so = (uint64_t)(s * 2);
            mma_f16_ss(tmem, ah + so, bh + so, IDESC_BF16_N64, s > 0 ? 1u : 0u);
            mma_f16_ss(tmem, ah + so, bl + so, IDESC_BF16_N64, 1u);
            mma_f16_ss(tmem, al + so, bh + so, IDESC_BF16_N64, 1u);
        }
        TCGEN05_COMMIT(m1);
    }
    uint32_t mbits = load_mask_bits(0);
    load_kt_regs(64);
    load_k_regs(0);

    int cnt = 0;

    for (int yt = 0; yt < 16; yt++) {
        // ---- wait MMA1(yt); LDTM S x32 + relu/mask/cnt (overlaps MMA2(yt-1)) ----
        MBARRIER_WAIT_PARITY(m1, yt & 1);
        TCGEN05_FENCE_AFTER();

        uint4 sh[2][2], sl[2][2];
        {
            uint32_t s0[32];
            TCGEN05_LD_32X32B_X32(s0, tmem + half * 32);
            TCGEN05_WAIT_LD();
            TCGEN05_FENCE_BEFORE();
#pragma unroll
            for (int h16 = 0; h16 < 2; h16++) {
                uint16_t hh[16], ll[16];
#pragma unroll
                for (int j = 0; j < 16; j++) {
                    float v = __uint_as_float(s0[h16 * 16 + j]);
                    v = v > 0.f ? v : 0.f;
                    uint32_t mb = (mbits >> (h16 * 16 + j)) & 1u;
                    v = mb ? v : 0.f;
                    cnt += (int)mb;
                    bf16_split(v, hh[j], ll[j]);
                }
#pragma unroll
                for (int g = 0; g < 2; g++) {
                    sh[h16][g] = make_uint4(
                        (uint32_t)hh[g*8+0] | ((uint32_t)hh[g*8+1] << 16),
                        (uint32_t)hh[g*8+2] | ((uint32_t)hh[g*8+3] << 16),
                        (uint32_t)hh[g*8+4] | ((uint32_t)hh[g*8+5] << 16),
                        (uint32_t)hh[g*8+6] | ((uint32_t)hh[g*8+7] << 16));
                    sl[h16][g] = make_uint4(
                        (uint32_t)ll[g*8+0] | ((uint32_t)ll[g*8+1] << 16),
                        (uint32_t)ll[g*8+2] | ((uint32_t)ll[g*8+3] << 16),
                        (uint32_t)ll[g*8+4] | ((uint32_t)ll[g*8+5] << 16),
                        (uint32_t)ll[g*8+6] | ((uint32_t)ll[g*8+7] << 16));
                }
            }
        }

        // ---- wait MMA2(yt-1): frees S and K buffers ----
        if (yt > 0) MBARRIER_WAIT_PARITY(m2, (yt - 1) & 1);

        // ---- store S'(yt), K(yt), KT(yt+1) ----
        {
            uint32_t off = (uint32_t)((x >> 3) * 1024 + (x & 7) * 128 + half * 64);
#pragma unroll
            for (int h16 = 0; h16 < 2; h16++)
#pragma unroll
                for (int g = 0; g < 2; g++) {
                    uint32_t sw = SW128(off + h16 * 32 + g * 16);
                    *(uint4*)(p + (SHI - base) + sw) = sh[h16][g];
                    *(uint4*)(p + (SLO - base) + sw) = sl[h16][g];
                }
        }
        store_k();
        if (yt + 1 < 16) store_kt();
        FENCE_PROXY_ASYNC_SHARED_CTA();
        __syncthreads();

        // ---- issue MMA2(yt) and MMA1(yt+1) back-to-back ----
        if (wid == 0 && elect_one_pred()) {
            {
                uint64_t ah = desc_k_major(SHI), al = desc_k_major(SLO);
                uint64_t bh = desc_k_major(KHI), bl = desc_k_major(KLO);
#pragma unroll
                for (int s = 0; s < 4; s++) {
                    uint64_t so = (uint64_t)(s * 2);
                    mma_f16_ss(tmem + 64, ah + so, bh + so, IDESC_BF16_N64,
                               (yt == 0 && s == 0) ? 0u : 1u);
                    mma_f16_ss(tmem + 64, ah + so, bl + so, IDESC_BF16_N64, 1u);
                    mma_f16_ss(tmem + 64, al + so, bh + so, IDESC_BF16_N64, 1u);
                }
                TCGEN05_COMMIT(m2);
            }
            if (yt + 1 < 16) {
                uint64_t ah = desc_k_major(QHI), al = desc_k_major(QLO);
                uint64_t bh = desc_k_major(KTHI), bl = desc_k_major(KTLO);
#pragma unroll
                for (int s = 0; s < 4; s++) {
                    uint64_t so = (uint64_t)(s * 2);
                    mma_f16_ss(tmem, ah + so, bh + so, IDESC_BF16_N64,
                               s > 0 ? 1u : 0u);
                    mma_f16_ss(tmem, ah + so, bl + so, IDESC_BF16_N64, 1u);
                    mma_f16_ss(tmem, al + so, bh + so, IDESC_BF16_N64, 1u);
                }
                TCGEN05_COMMIT(m1);
            }
        }

        // ---- prefetch next mask/K/KT regs (overlaps both MMAs) ----
        if (yt + 1 < 16) {
            mbits = load_mask_bits((yt + 1) * 64);
            load_k_regs((yt + 1) * 64);
            if (yt + 2 < 16) load_kt_regs((yt + 2) * 64);
        }
    }

    // final MMA2(15) completion: phase 15 -> parity 1
    MBARRIER_WAIT_PARITY(m2, 1);
    TCGEN05_FENCE_AFTER();

    // ---- epilogue: combine counts, normalize, transpose via d-major scr ----
    {
        float* scr = (float*)p;
        __syncthreads();
        cnts[half * 128 + x] = cnt;
        __syncthreads();
        int tot = cnts[x] + cnts[128 + x];
        float inv = 1.0f / (float)(tot > 0 ? tot : 1);
#pragma unroll
        for (int h16 = 0; h16 < 2; h16++) {
            uint32_t c0[16];
            TCGEN05_LD_32X32B_X16(c0, tmem + 64 + half * 32 + h16 * 16);
            TCGEN05_WAIT_LD();
            TCGEN05_FENCE_BEFORE();
#pragma unroll
            for (int j = 0; j < 16; j++) {
                float v = __uint_as_float(c0[j]) * inv;
                scr[(half * 32 + h16 * 16 + j) * 132 + x] = v;
            }
        }
        __syncthreads();
        float* Cb = C + ((size_t)(b * U_ + h * D_)) * L_ + x0;
#pragma unroll 2
        for (int t = 0; t < 8; t++) {
            int idx = tid + t * 256;
            int d  = idx >> 5;
            int x4 = (idx & 31) << 2;
            float4 v = *(float4*)&scr[d * 132 + x4];
            *(float4*)(Cb + (size_t)d * L_ + x4) = v;
        }
    }
    __syncthreads();
    if (wid == 0) TCGEN05_DEALLOC(tmem, 256);
#else
    (void)Q; (void)K; (void)mask; (void)C;
#endif
}

// ---------------------------------------------------------------------------
extern "C" void kernel_launch(void* const* d_in, const int* in_sizes, int n_in,
                              void* d_out, int out_size)
{
    const float* x  = (const float*)d_in[0];
    const float* y  = (const float*)d_in[1];
    const int*   mk = (const int*)d_in[2];
    const float* wq = (const float*)d_in[3];
    const float* wk = (const float*)d_in[4];
    const float* wo = (const float*)d_in[5];
    float* out = (float*)d_out;

    float *Qp, *Kp, *Cp;
    cudaGetSymbolAddress((void**)&Qp, g_Q);
    cudaGetSymbolAddress((void**)&Kp, g_K);
    cudaGetSymbolAddress((void**)&Cp, g_C);

    cudaFuncSetAttribute(tc_gemm<false>, cudaFuncAttributeMaxDynamicSharedMemorySize,
                         TCG_SMEM_BYTES);
    cudaFuncSetAttribute(tc_gemm<true>, cudaFuncAttributeMaxDynamicSharedMemorySize,
                         TCG_SMEM_BYTES);
    cudaFuncSetAttribute(attn_tc, cudaFuncAttributeMaxDynamicSharedMemorySize,
                         AT_SMEM_BYTES);

    // fused Q+K projection: z in [0,16) -> Q=wq*x, z in [16,32) -> K=wk*y
    tc_gemm<false><<<dim3(L_ / 128, U_ / 128, 2 * B_), 256, TCG_SMEM_BYTES>>>(
        wq, x, wk, y, nullptr, Qp, Kp);
    attn_tc<<<dim3(H_, L_ / 128, B_), 256, AT_SMEM_BYTES>>>(Qp, Kp, mk, Cp);
    tc_gemm<true><<<dim3(L_ / 128, U_ / 128, B_), 256, TCG_SMEM_BYTES>>>(
        wo, Qp, nullptr, nullptr, Cp, out, nullptr);
}

// round 15
// speedup vs baseline: 1.2362x; 1.2362x over previous
#include <cuda_runtime.h>
#include <cuda_bf16.h>
#include <cstdint>
#include <cstddef>

// Problem constants
#define B_  16
#define U_  512
#define L_  1024
#define H_  8
#define D_  64
#define SCALE_ 0.125f   // 1/sqrt(64)

// Scratch (device globals — allocation-free rule).
__device__ __align__(256) float g_Q[(size_t)B_ * U_ * L_];
__device__ __align__(256) float g_K[(size_t)B_ * U_ * L_];
__device__ __align__(256) float g_C[(size_t)B_ * U_ * L_];

// ===========================================================================
// Arch gating
// ===========================================================================
#if defined(__CUDA_ARCH_FEAT_SM103_ALL) || defined(__CUDA_ARCH_FEAT_SM100_ALL) || \
    defined(__CUDA_ARCH_FAMILY_SPECIFIC__) || defined(__CUDA_ARCH_SPECIFIC__)
#define TC_OK 1
#else
#define TC_OK 0
#endif

__device__ __forceinline__ uint32_t smem_to_u32(const void* p) {
    uint32_t a;
    asm("{ .reg .u64 t; cvta.to.shared.u64 t, %1; cvt.u32.u64 %0, t; }" : "=r"(a) : "l"(p));
    return a;
}
#define MBARRIER_INIT(mbar, count) \
    asm volatile("mbarrier.init.shared.b64 [%0], %1;" \
                 :: "r"((uint32_t)(mbar)), "r"((uint32_t)(count)) : "memory")
#define MBARRIER_WAIT_PARITY(mbar, parity) do {                                   \
    uint32_t _m = (uint32_t)(mbar); uint32_t _p = (uint32_t)(parity);             \
    asm volatile("{\n\t.reg .pred P1;\n\t"                                        \
        "WAIT_LOOP_%=:\n\t"                                                        \
        "mbarrier.try_wait.parity.acquire.cta.shared::cta.b64 P1, [%0], %1, 0x989680;\n\t" \
        "@P1 bra.uni WAIT_DONE_%=;\n\t"                                            \
        "bra.uni WAIT_LOOP_%=;\n\t"                                                \
        "WAIT_DONE_%=:\n\t}" :: "r"(_m), "r"(_p) : "memory");                      \
} while (0)
#define FENCE_PROXY_ASYNC_SHARED_CTA() asm volatile("fence.proxy.async.shared::cta;" ::: "memory")

#if TC_OK
__device__ __forceinline__ uint32_t elect_one_pred() {
    uint32_t pred;
    asm volatile("{\n\t.reg .pred p;\n\telect.sync _|p, 0xFFFFFFFF;\n\tselp.b32 %0, 1, 0, p;\n\t}"
                 : "=r"(pred));
    return pred;
}
#define TCGEN05_ALLOC(smem_result_addr, nCols) \
    asm volatile("tcgen05.alloc.cta_group::1.sync.aligned.shared::cta.b32 [%0], %1;" \
                 :: "r"((uint32_t)(smem_result_addr)), "r"((uint32_t)(nCols)) : "memory")
#define TCGEN05_DEALLOC(tmem_addr, nCols) \
    asm volatile("tcgen05.dealloc.cta_group::1.sync.aligned.b32 %0, %1;" \
                 :: "r"(tmem_addr), "r"((uint32_t)(nCols)))
#define TCGEN05_RELINQUISH() \
    asm volatile("tcgen05.relinquish_alloc_permit.cta_group::1.sync.aligned;")
#define TCGEN05_COMMIT(mbar) \
    asm volatile("tcgen05.commit.cta_group::1.mbarrier::arrive::one.shared::cluster.b64 [%0];" \
                 :: "r"((uint32_t)(mbar)) : "memory")
#define TCGEN05_FENCE_BEFORE() asm volatile("tcgen05.fence::before_thread_sync;" ::: "memory")
#define TCGEN05_FENCE_AFTER()  asm volatile("tcgen05.fence::after_thread_sync;"  ::: "memory")
#define TCGEN05_WAIT_LD()      asm volatile("tcgen05.wait::ld.sync.aligned;"     ::: "memory")
#define TCGEN05_LD_32X32B_X32(r, tmem_addr) \
    asm volatile( \
        "tcgen05.ld.sync.aligned.32x32b.x32.b32 " \
        "{%0, %1, %2, %3, %4, %5, %6, %7, " \
        " %8, %9, %10, %11, %12, %13, %14, %15, " \
        " %16, %17, %18, %19, %20, %21, %22, %23, " \
        " %24, %25, %26, %27, %28, %29, %30, %31}, [%32];" \
        : "=r"((r)[0]),  "=r"((r)[1]),  "=r"((r)[2]),  "=r"((r)[3]), \
          "=r"((r)[4]),  "=r"((r)[5]),  "=r"((r)[6]),  "=r"((r)[7]), \
          "=r"((r)[8]),  "=r"((r)[9]),  "=r"((r)[10]), "=r"((r)[11]), \
          "=r"((r)[12]), "=r"((r)[13]), "=r"((r)[14]), "=r"((r)[15]), \
          "=r"((r)[16]), "=r"((r)[17]), "=r"((r)[18]), "=r"((r)[19]), \
          "=r"((r)[20]), "=r"((r)[21]), "=r"((r)[22]), "=r"((r)[23]), \
          "=r"((r)[24]), "=r"((r)[25]), "=r"((r)[26]), "=r"((r)[27]), \
          "=r"((r)[28]), "=r"((r)[29]), "=r"((r)[30]), "=r"((r)[31]) \
        : "r"(tmem_addr))
#define TCGEN05_LD_32X32B_X16(r, tmem_addr) \
    asm volatile( \
        "tcgen05.ld.sync.aligned.32x32b.x16.b32 " \
        "{%0, %1, %2, %3, %4, %5, %6, %7, " \
        " %8, %9, %10, %11, %12, %13, %14, %15}, [%16];" \
        : "=r"((r)[0]),  "=r"((r)[1]),  "=r"((r)[2]),  "=r"((r)[3]), \
          "=r"((r)[4]),  "=r"((r)[5]),  "=r"((r)[6]),  "=r"((r)[7]), \
          "=r"((r)[8]),  "=r"((r)[9]),  "=r"((r)[10]), "=r"((r)[11]), \
          "=r"((r)[12]), "=r"((r)[13]), "=r"((r)[14]), "=r"((r)[15]) \
        : "r"(tmem_addr))

__device__ __forceinline__ void mma_f16_ss(uint32_t d_tmem, uint64_t a_desc,
                                           uint64_t b_desc, uint32_t idesc,
                                           uint32_t enable) {
    asm volatile(
        "{\n\t"
        ".reg .pred p;\n\t"
        "setp.ne.u32 p, %5, 0;\n\t"
        "tcgen05.mma.cta_group::1.kind::f16 [%0], %1, %2, %3, {%4, %4, %4, %4}, p;\n\t"
        "}"
        :: "r"(d_tmem), "l"(a_desc), "l"(b_desc), "r"(idesc), "r"(0u), "r"(enable)
        : "memory");
}
#endif  // TC_OK

// K-major SW128 descriptor
__device__ __forceinline__ uint64_t desc_k_major(uint32_t addr) {
    return ((uint64_t)(addr >> 4) & 0x3FFF)
         | (1ull << 16) | (64ull << 32) | (1ull << 46) | (2ull << 61);
}

#define SW128(off) ((off) ^ (((off) >> 3) & 0x70))

#define IDESC_BF16_N128 0x8200490u
#define IDESC_BF16_N64  0x8100490u

// Fast pair split: hi = bf16-truncation (exact residual), lo = rn-bf16(x-hi).
// hp = {hi(v1):hi(v0)} via one PRMT; lp = {lo(v1):lo(v0)} via one cvt.bf16x2.
__device__ __forceinline__ void bf16_split2(float v0, float v1,
                                            uint32_t& hp, uint32_t& lp) {
    uint32_t u0 = __float_as_uint(v0), u1 = __float_as_uint(v1);
    asm("prmt.b32 %0, %1, %2, 0x7632;" : "=r"(hp) : "r"(u0), "r"(u1));
    float l0 = v0 - __uint_as_float(u0 & 0xFFFF0000u);
    float l1 = v1 - __uint_as_float(u1 & 0xFFFF0000u);
    asm("cvt.rn.bf16x2.f32 %0, %1, %2;" : "=r"(lp) : "f"(l1), "f"(l0));
}

// ===========================================================================
// tcgen05 split-bf16 channel-mix GEMM (R12 structure, fast convert).
// ===========================================================================
#define TCG_SMEM_BYTES 66688

template <bool FUSE>
__global__ __launch_bounds__(256, 2) __cluster_dims__(1, 1, 1) void tc_gemm(
    const float* __restrict__ Wa, const float* __restrict__ Xa,
    const float* __restrict__ Wb, const float* __restrict__ Xb,
    const float* __restrict__ X2, float* __restrict__ OutA,
    float* __restrict__ OutB)
{
#if TC_OK
    extern __shared__ uint8_t dsm[];
    const uint32_t raw  = smem_to_u32(dsm);
    const uint32_t base = (raw + 1023u) & ~1023u;
    uint8_t* p = dsm + (base - raw);

    const uint32_t ctrl = base + 65536;
    const uint32_t mbar = ctrl + 8;

    const float* W; const float* X1; float* Out; int b;
    if (blockIdx.z < B_) { W = Wa; X1 = Xa; Out = OutA; b = blockIdx.z; }
    else                 { W = Wb; X1 = Xb; Out = OutB; b = blockIdx.z - B_; }

    const int row0 = blockIdx.y * 128;
    const int col0 = blockIdx.x * 128;
    const int tid  = threadIdx.x;
    const int wid  = tid >> 5;
    const int lid  = tid & 31;

    if (wid == 0) {
        TCGEN05_ALLOC(ctrl, 256);
        TCGEN05_RELINQUISH();
    }
    if (tid == 0) MBARRIER_INIT(mbar, 1);
    __syncthreads();
    uint32_t tmem;
    asm volatile("ld.shared.b32 %0, [%1];" : "=r"(tmem) : "r"(ctrl));

    const float* Wb_  = W + (size_t)row0 * U_;
    const float* X1b = X1 + (size_t)b * U_ * L_ + col0;
    const float* X2b = FUSE ? (X2 + (size_t)b * U_ * L_ + col0) : nullptr;

    float4 aR[8];
    float  bR[4][8];

    auto load_regs = [&](int c) {
        const int k0 = c * 64;
#pragma unroll
        for (int t = 0; t < 8; t++) {
            int idx = tid + t * 256;
            int m  = idx >> 4;
            int k4 = (idx & 15) << 2;
            aR[t] = *(const float4*)(Wb_ + (size_t)m * U_ + k0 + k4);
        }
#pragma unroll
        for (int ei = 0; ei < 4; ei++) {
            int n = lid + 32 * ei;
#pragma unroll
            for (int kk = 0; kk < 8; kk++) {
                size_t ro = (size_t)(k0 + wid * 8 + kk) * L_ + n;
                float v = X1b[ro];
                if (FUSE) v = 0.5f * (v + X2b[ro]);
                bR[ei][kk] = v;
            }
        }
    };

    auto store_stage = [&]() {
#pragma unroll
        for (int t = 0; t < 8; t++) {
            int idx = tid + t * 256;
            int m  = idx >> 4;
            int k4 = (idx & 15) << 2;
            float4 v = aR[t];
            uint32_t h0, l0, h1, l1;
            bf16_split2(v.x, v.y, h0, l0);
            bf16_split2(v.z, v.w, h1, l1);
            uint32_t off = (uint32_t)((m >> 3) * 1024 + (m & 7) * 128 + k4 * 2);
            uint32_t sw = SW128(off);
            *(uint2*)(p + sw)         = make_uint2(h0, h1);
            *(uint2*)(p + 16384 + sw) = make_uint2(l0, l1);
        }
#pragma unroll
        for (int ei = 0; ei < 4; ei++) {
            int n = lid + 32 * ei;
            uint32_t hp[4], lp[4];
#pragma unroll
            for (int kk = 0; kk < 4; kk++)
                bf16_split2(bR[ei][2 * kk], bR[ei][2 * kk + 1], hp[kk], lp[kk]);
            uint32_t off = (uint32_t)((n >> 3) * 1024 + (n & 7) * 128 + wid * 16);
            uint32_t sw = SW128(off);
            *(uint4*)(p + 32768 + sw) = make_uint4(hp[0], hp[1], hp[2], hp[3]);
            *(uint4*)(p + 49152 + sw) = make_uint4(lp[0], lp[1], lp[2], lp[3]);
        }
        FENCE_PROXY_ASYNC_SHARED_CTA();
    };

    load_regs(0);
    store_stage();
    __syncthreads();

    const int NC = U_ / 64;   // 8 chunks
    for (int c = 0; c < NC; c++) {
        if (wid == 0 && elect_one_pred()) {
            uint64_t ahi = desc_k_major(base);
            uint64_t alo = desc_k_major(base + 16384);
            uint64_t bhi = desc_k_major(base + 32768);
            uint64_t blo = desc_k_major(base + 49152);
#pragma unroll
            for (int s = 0; s < 4; s++) {
                uint64_t so = (uint64_t)(s * 2);
                mma_f16_ss(tmem, ahi + so, bhi + so, IDESC_BF16_N128,
                           (c == 0 && s == 0) ? 0u : 1u);
                mma_f16_ss(tmem, ahi + so, blo + so, IDESC_BF16_N128, 1u);
                mma_f16_ss(tmem, alo + so, bhi + so, IDESC_BF16_N128, 1u);
            }
            TCGEN05_COMMIT(mbar);
        }
        if (c + 1 < NC) load_regs(c + 1);
        MBARRIER_WAIT_PARITY(mbar, c & 1);
        if (c + 1 < NC) {
            store_stage();
            __syncthreads();
        }
    }

    TCGEN05_FENCE_AFTER();

    if (wid < 4) {
        const int m = wid * 32 + lid;
        float* op = Out + ((size_t)b * U_ + row0 + m) * L_ + col0;
#pragma unroll
        for (int j = 0; j < 4; j++) {
            uint32_t r32[32];
            TCGEN05_LD_32X32B_X32(r32, tmem + j * 32);
            TCGEN05_WAIT_LD();
            TCGEN05_FENCE_BEFORE();
#pragma unroll
            for (int q = 0; q < 8; q++) {
                float4 v = make_float4(__uint_as_float(r32[q * 4 + 0]),
                                       __uint_as_float(r32[q * 4 + 1]),
                                       __uint_as_float(r32[q * 4 + 2]),
                                       __uint_as_float(r32[q * 4 + 3]));
                *(float4*)(op + j * 32 + q * 4) = v;
            }
        }
    }
    __syncthreads();
    if (wid == 0) TCGEN05_DEALLOC(tmem, 256);
#else
    (void)Wa; (void)Xa; (void)Wb; (void)Xb; (void)X2; (void)OutA; (void)OutB;
#endif
}

// ===========================================================================
// tcgen05 attention — R13 scheduling, fast convert.
// smem: QHI 0 | QLO 16384 | KTHI 32768 | KTLO 40960 | KHI 49152 | KLO 57344
//       SHI 65536 | SLO 81920 | ctrl 98304 | cnts 98336
// ===========================================================================
#define AT_SMEM_BYTES 100384

__global__ __launch_bounds__(256, 2) __cluster_dims__(1, 1, 1) void attn_tc(
    const float* __restrict__ Q, const float* __restrict__ K,
    const int* __restrict__ mask, float* __restrict__ C)
{
#if TC_OK
    extern __shared__ uint8_t dsm[];
    const uint32_t raw  = smem_to_u32(dsm);
    const uint32_t base = (raw + 1023u) & ~1023u;
    uint8_t* p = dsm + (base - raw);

    const uint32_t QHI = base, QLO = base + 16384;
    const uint32_t KTHI = base + 32768, KTLO = base + 40960;
    const uint32_t KHI = base + 49152, KLO = base + 57344;
    const uint32_t SHI = base + 65536, SLO = base + 81920;
    const uint32_t ctrl = base + 98304;
    const uint32_t m1 = ctrl + 8;
    const uint32_t m2 = ctrl + 16;
    int* cnts = (int*)(p + 98336);

    const int b  = blockIdx.z;
    const int h  = blockIdx.x;
    const int x0 = blockIdx.y * 128;
    const int tid = threadIdx.x;
    const int wid = tid >> 5;
    const int lid = tid & 31;
    const int sub  = wid & 3;
    const int half = wid >> 2;

    if (wid == 0) {
        TCGEN05_ALLOC(ctrl, 256);
        TCGEN05_RELINQUISH();
    }
    if (tid == 0) { MBARRIER_INIT(m1, 1); MBARRIER_INIT(m2, 1); }
    __syncthreads();
    uint32_t tmem;
    asm volatile("ld.shared.b32 %0, [%1];" : "=r"(tmem) : "r"(ctrl));

    const float* Qb = Q + ((size_t)(b * U_ + h * D_)) * L_ + x0;
    const float* Kb = K + ((size_t)(b * U_ + h * D_)) * L_;
    const int*   Mb = mask + ((size_t)b * L_ + x0) * L_;

    const int x = sub * 32 + lid;

    // ---- stage Q^T [128x][64d] hi/lo (scale folded), once ----
#pragma unroll
    for (int ei = 0; ei < 4; ei++) {
        int xq = lid + 32 * ei;
        float rv[8];
#pragma unroll
        for (int kk = 0; kk < 8; kk++)
            rv[kk] = Qb[(size_t)(wid * 8 + kk) * L_ + xq] * SCALE_;
        uint32_t hp[4], lp[4];
#pragma unroll
        for (int kk = 0; kk < 4; kk++)
            bf16_split2(rv[2 * kk], rv[2 * kk + 1], hp[kk], lp[kk]);
        uint32_t sw = SW128((uint32_t)((xq >> 3) * 1024 + (xq & 7) * 128 + wid * 16));
        *(uint4*)(p + (QHI - base) + sw) = make_uint4(hp[0], hp[1], hp[2], hp[3]);
        *(uint4*)(p + (QLO - base) + sw) = make_uint4(lp[0], lp[1], lp[2], lp[3]);
    }

    float  ktR[2][8];
    float4 kR[4];

    auto load_kt_regs = [&](int y0n) {
#pragma unroll
        for (int ei = 0; ei < 2; ei++) {
            int y = lid + 32 * ei;
#pragma unroll
            for (int kk = 0; kk < 8; kk++)
                ktR[ei][kk] = Kb[(size_t)(wid * 8 + kk) * L_ + y0n + y];
        }
    };
    auto load_k_regs = [&](int y0n) {
#pragma unroll
        for (int t = 0; t < 4; t++) {
            int idx = tid + t * 256;
            int d  = idx >> 4;
            int y4 = (idx & 15) << 2;
            kR[t] = *(const float4*)(Kb + (size_t)d * L_ + y0n + y4);
        }
    };
    auto store_kt = [&]() {
#pragma unroll
        for (int ei = 0; ei < 2; ei++) {
            int y = lid + 32 * ei;
            uint32_t hp[4], lp[4];
#pragma unroll
            for (int kk = 0; kk < 4; kk++)
                bf16_split2(ktR[ei][2 * kk], ktR[ei][2 * kk + 1], hp[kk], lp[kk]);
            uint32_t sw = SW128((uint32_t)((y >> 3) * 1024 + (y & 7) * 128 + wid * 16));
            *(uint4*)(p + (KTHI - base) + sw) = make_uint4(hp[0], hp[1], hp[2], hp[3]);
            *(uint4*)(p + (KTLO - base) + sw) = make_uint4(lp[0], lp[1], lp[2], lp[3]);
        }
    };
    auto store_k = [&]() {
#pragma unroll
        for (int t = 0; t < 4; t++) {
            int idx = tid + t * 256;
            int d  = idx >> 4;
            int y4 = (idx & 15) << 2;
            float4 v = kR[t];
            uint32_t h0, l0, h1, l1;
            bf16_split2(v.x, v.y, h0, l0);
            bf16_split2(v.z, v.w, h1, l1);
            uint32_t sw = SW128((uint32_t)((d >> 3) * 1024 + (d & 7) * 128 + y4 * 2));
            *(uint2*)(p + (KHI - base) + sw) = make_uint2(h0, h1);
            *(uint2*)(p + (KLO - base) + sw) = make_uint2(l0, l1);
        }
    };

    // prologue
    load_kt_regs(0);
    store_kt();
    FENCE_PROXY_ASYNC_SHARED_CTA();
    __syncthreads();
    if (wid == 0 && elect_one_pred()) {
        uint64_t ah = desc_k_major(QHI), al = desc_k_major(QLO);
        uint64_t bh = desc_k_major(KTHI), bl = desc_k_major(KTLO);
#pragma unroll
        for (int s = 0; s < 4; s++) {
            uint64_t so = (uint64_t)(s * 2);
            mma_f16_ss(tmem, ah + so, bh + so, IDESC_BF16_N64, s > 0 ? 1u : 0u);
            mma_f16_ss(tmem, ah + so, bl + so, IDESC_BF16_N64, 1u);
            mma_f16_ss(tmem, al + so, bh + so, IDESC_BF16_N64, 1u);
        }
        TCGEN05_COMMIT(m1);
    }
    load_kt_regs(64);
    load_k_regs(0);

    int cnt = 0;

    for (int yt = 0; yt < 16; yt++) {
        MBARRIER_WAIT_PARITY(m1, yt & 1);
        TCGEN05_FENCE_AFTER();

        uint4 sh[2][2], sl[2][2];
        const int* mrow = Mb + (size_t)x * L_ + yt * 64 + half * 32;
#pragma unroll
        for (int h16 = 0; h16 < 2; h16++) {
            uint32_t s0[16];
            TCGEN05_LD_32X32B_X16(s0, tmem + half * 32 + h16 * 16);
            TCGEN05_WAIT_LD();
            TCGEN05_FENCE_BEFORE();
            int4 m0 = *(const int4*)(mrow + h16 * 16 + 0);
            int4 m1v = *(const int4*)(mrow + h16 * 16 + 4);
            int4 m2v = *(const int4*)(mrow + h16 * 16 + 8);
            int4 m3 = *(const int4*)(mrow + h16 * 16 + 12);
            int mv[16] = {m0.x, m0.y, m0.z, m0.w, m1v.x, m1v.y, m1v.z, m1v.w,
                          m2v.x, m2v.y, m2v.z, m2v.w, m3.x, m3.y, m3.z, m3.w};
            float fv[16];
#pragma unroll
            for (int j = 0; j < 16; j++) {
                float v = __uint_as_float(s0[j]);
                v = v > 0.f ? v : 0.f;
                v = mv[j] ? v : 0.f;
                cnt += mv[j] ? 1 : 0;
                fv[j] = v;
            }
            uint32_t hp[8], lp[8];
#pragma unroll
            for (int j = 0; j < 8; j++)
                bf16_split2(fv[2 * j], fv[2 * j + 1], hp[j], lp[j]);
            sh[h16][0] = make_uint4(hp[0], hp[1], hp[2], hp[3]);
            sh[h16][1] = make_uint4(hp[4], hp[5], hp[6], hp[7]);
            sl[h16][0] = make_uint4(lp[0], lp[1], lp[2], lp[3]);
            sl[h16][1] = make_uint4(lp[4], lp[5], lp[6], lp[7]);
        }

        if (yt > 0) MBARRIER_WAIT_PARITY(m2, (yt - 1) & 1);

        {
            uint32_t off = (uint32_t)((x >> 3) * 1024 + (x & 7) * 128 + half * 64);
#pragma unroll
            for (int h16 = 0; h16 < 2; h16++)
#pragma unroll
                for (int g = 0; g < 2; g++) {
                    uint32_t sw = SW128(off + h16 * 32 + g * 16);
                    *(uint4*)(p + (SHI - base) + sw) = sh[h16][g];
                    *(uint4*)(p + (SLO - base) + sw) = sl[h16][g];
                }
        }
        store_k();
        if (yt + 1 < 16) store_kt();
        FENCE_PROXY_ASYNC_SHARED_CTA();
        __syncthreads();

        if (wid == 0 && elect_one_pred()) {
            {
                uint64_t ah = desc_k_major(SHI), al = desc_k_major(SLO);
                uint64_t bh = desc_k_major(KHI), bl = desc_k_major(KLO);
#pragma unroll
                for (int s = 0; s < 4; s++) {
                    uint64_t so = (uint64_t)(s * 2);
                    mma_f16_ss(tmem + 64, ah + so, bh + so, IDESC_BF16_N64,
                               (yt == 0 && s == 0) ? 0u : 1u);
                    mma_f16_ss(tmem + 64, ah + so, bl + so, IDESC_BF16_N64, 1u);
                    mma_f16_ss(tmem + 64, al + so, bh + so, IDESC_BF16_N64, 1u);
                }
                TCGEN05_COMMIT(m2);
            }
            if (yt + 1 < 16) {
                uint64_t ah = desc_k_major(QHI), al = desc_k_major(QLO);
                uint64_t bh = desc_k_major(KTHI), bl = desc_k_major(KTLO);
#pragma unroll
                for (int s = 0; s < 4; s++) {
                    uint64_t so = (uint64_t)(s * 2);
                    mma_f16_ss(tmem, ah + so, bh + so, IDESC_BF16_N64,
                               s > 0 ? 1u : 0u);
                    mma_f16_ss(tmem, ah + so, bl + so, IDESC_BF16_N64, 1u);
                    mma_f16_ss(tmem, al + so, bh + so, IDESC_BF16_N64, 1u);
                }
                TCGEN05_COMMIT(m1);
            }
        }

        if (yt + 1 < 16) {
            load_k_regs((yt + 1) * 64);
            if (yt + 2 < 16) load_kt_regs((yt + 2) * 64);
        }
    }

    MBARRIER_WAIT_PARITY(m2, 1);
    TCGEN05_FENCE_AFTER();

    {
        float* scr = (float*)p;
        __syncthreads();
        cnts[half * 128 + x] = cnt;
        __syncthreads();
        int tot = cnts[x] + cnts[128 + x];
        float inv = 1.0f / (float)(tot > 0 ? tot : 1);
#pragma unroll
        for (int h16 = 0; h16 < 2; h16++) {
            uint32_t c0[16];
            TCGEN05_LD_32X32B_X16(c0, tmem + 64 + half * 32 + h16 * 16);
            TCGEN05_WAIT_LD();
            TCGEN05_FENCE_BEFORE();
#pragma unroll
            for (int j = 0; j < 16; j++) {
                float v = __uint_as_float(c0[j]) * inv;
                scr[(half * 32 + h16 * 16 + j) * 132 + x] = v;
            }
        }
        __syncthreads();
        float* Cb = C + ((size_t)(b * U_ + h * D_)) * L_ + x0;
#pragma unroll 2
        for (int t = 0; t < 8; t++) {
            int idx = tid + t * 256;
            int d  = idx >> 5;
            int x4 = (idx & 31) << 2;
            float4 v = *(float4*)&scr[d * 132 + x4];
            *(float4*)(Cb + (size_t)d * L_ + x4) = v;
        }
    }
    __syncthreads();
    if (wid == 0) TCGEN05_DEALLOC(tmem, 256);
#else
    (void)Q; (void)K; (void)mask; (void)C;
#endif
}

// ---------------------------------------------------------------------------
extern "C" void kernel_launch(void* const* d_in, const int* in_sizes, int n_in,
                              void* d_out, int out_size)
{
    const float* x  = (const float*)d_in[0];
    const float* y  = (const float*)d_in[1];
    const int*   mk = (const int*)d_in[2];
    const float* wq = (const float*)d_in[3];
    const float* wk = (const float*)d_in[4];
    const float* wo = (const float*)d_in[5];
    float* out = (float*)d_out;

    float *Qp, *Kp, *Cp;
    cudaGetSymbolAddress((void**)&Qp, g_Q);
    cudaGetSymbolAddress((void**)&Kp, g_K);
    cudaGetSymbolAddress((void**)&Cp, g_C);

    cudaFuncSetAttribute(tc_gemm<false>, cudaFuncAttributeMaxDynamicSharedMemorySize,
                         TCG_SMEM_BYTES);
    cudaFuncSetAttribute(tc_gemm<true>, cudaFuncAttributeMaxDynamicSharedMemorySize,
                         TCG_SMEM_BYTES);
    cudaFuncSetAttribute(attn_tc, cudaFuncAttributeMaxDynamicSharedMemorySize,
                         AT_SMEM_BYTES);

    // fused Q+K projection: z in [0,16) -> Q=wq*x, z in [16,32) -> K=wk*y
    tc_gemm<false><<<dim3(L_ / 128, U_ / 128, 2 * B_), 256, TCG_SMEM_BYTES>>>(
        wq, x, wk, y, nullptr, Qp, Kp);
    attn_tc<<<dim3(H_, L_ / 128, B_), 256, AT_SMEM_BYTES>>>(Qp, Kp, mk, Cp);
    tc_gemm<true><<<dim3(L_ / 128, U_ / 128, B_), 256, TCG_SMEM_BYTES>>>(
        wo, Qp, nullptr, nullptr, Cp, out, nullptr);
}

// round 16
// speedup vs baseline: 1.2689x; 1.0265x over previous
#include <cuda_runtime.h>
#include <cuda_bf16.h>
#include <cstdint>
#include <cstddef>

// Problem constants
#define B_  16
#define U_  512
#define L_  1024
#define H_  8
#define D_  64
#define SCALE_ 0.125f   // 1/sqrt(64)

// Scratch (device globals — allocation-free rule).
__device__ __align__(256) float g_Q[(size_t)B_ * U_ * L_];
__device__ __align__(256) float g_K[(size_t)B_ * U_ * L_];
__device__ __align__(256) float g_C[(size_t)B_ * U_ * L_];

// ===========================================================================
// Arch gating
// ===========================================================================
#if defined(__CUDA_ARCH_FEAT_SM103_ALL) || defined(__CUDA_ARCH_FEAT_SM100_ALL) || \
    defined(__CUDA_ARCH_FAMILY_SPECIFIC__) || defined(__CUDA_ARCH_SPECIFIC__)
#define TC_OK 1
#else
#define TC_OK 0
#endif

__device__ __forceinline__ uint32_t smem_to_u32(const void* p) {
    uint32_t a;
    asm("{ .reg .u64 t; cvta.to.shared.u64 t, %1; cvt.u32.u64 %0, t; }" : "=r"(a) : "l"(p));
    return a;
}
#define MBARRIER_INIT(mbar, count) \
    asm volatile("mbarrier.init.shared.b64 [%0], %1;" \
                 :: "r"((uint32_t)(mbar)), "r"((uint32_t)(count)) : "memory")
#define MBARRIER_WAIT_PARITY(mbar, parity) do {                                   \
    uint32_t _m = (uint32_t)(mbar); uint32_t _p = (uint32_t)(parity);             \
    asm volatile("{\n\t.reg .pred P1;\n\t"                                        \
        "WAIT_LOOP_%=:\n\t"                                                        \
        "mbarrier.try_wait.parity.acquire.cta.shared::cta.b64 P1, [%0], %1, 0x989680;\n\t" \
        "@P1 bra.uni WAIT_DONE_%=;\n\t"                                            \
        "bra.uni WAIT_LOOP_%=;\n\t"                                                \
        "WAIT_DONE_%=:\n\t}" :: "r"(_m), "r"(_p) : "memory");                      \
} while (0)
#define FENCE_PROXY_ASYNC_SHARED_CTA() asm volatile("fence.proxy.async.shared::cta;" ::: "memory")

#if TC_OK
__device__ __forceinline__ uint32_t elect_one_pred() {
    uint32_t pred;
    asm volatile("{\n\t.reg .pred p;\n\telect.sync _|p, 0xFFFFFFFF;\n\tselp.b32 %0, 1, 0, p;\n\t}"
                 : "=r"(pred));
    return pred;
}
#define TCGEN05_ALLOC(smem_result_addr, nCols) \
    asm volatile("tcgen05.alloc.cta_group::1.sync.aligned.shared::cta.b32 [%0], %1;" \
                 :: "r"((uint32_t)(smem_result_addr)), "r"((uint32_t)(nCols)) : "memory")
#define TCGEN05_DEALLOC(tmem_addr, nCols) \
    asm volatile("tcgen05.dealloc.cta_group::1.sync.aligned.b32 %0, %1;" \
                 :: "r"(tmem_addr), "r"((uint32_t)(nCols)))
#define TCGEN05_RELINQUISH() \
    asm volatile("tcgen05.relinquish_alloc_permit.cta_group::1.sync.aligned;")
#define TCGEN05_COMMIT(mbar) \
    asm volatile("tcgen05.commit.cta_group::1.mbarrier::arrive::one.shared::cluster.b64 [%0];" \
                 :: "r"((uint32_t)(mbar)) : "memory")
#define TCGEN05_FENCE_BEFORE() asm volatile("tcgen05.fence::before_thread_sync;" ::: "memory")
#define TCGEN05_FENCE_AFTER()  asm volatile("tcgen05.fence::after_thread_sync;"  ::: "memory")
#define TCGEN05_WAIT_LD()      asm volatile("tcgen05.wait::ld.sync.aligned;"     ::: "memory")
#define TCGEN05_LD_32X32B_X32(r, tmem_addr) \
    asm volatile( \
        "tcgen05.ld.sync.aligned.32x32b.x32.b32 " \
        "{%0, %1, %2, %3, %4, %5, %6, %7, " \
        " %8, %9, %10, %11, %12, %13, %14, %15, " \
        " %16, %17, %18, %19, %20, %21, %22, %23, " \
        " %24, %25, %26, %27, %28, %29, %30, %31}, [%32];" \
        : "=r"((r)[0]),  "=r"((r)[1]),  "=r"((r)[2]),  "=r"((r)[3]), \
          "=r"((r)[4]),  "=r"((r)[5]),  "=r"((r)[6]),  "=r"((r)[7]), \
          "=r"((r)[8]),  "=r"((r)[9]),  "=r"((r)[10]), "=r"((r)[11]), \
          "=r"((r)[12]), "=r"((r)[13]), "=r"((r)[14]), "=r"((r)[15]), \
          "=r"((r)[16]), "=r"((r)[17]), "=r"((r)[18]), "=r"((r)[19]), \
          "=r"((r)[20]), "=r"((r)[21]), "=r"((r)[22]), "=r"((r)[23]), \
          "=r"((r)[24]), "=r"((r)[25]), "=r"((r)[26]), "=r"((r)[27]), \
          "=r"((r)[28]), "=r"((r)[29]), "=r"((r)[30]), "=r"((r)[31]) \
        : "r"(tmem_addr))
#define TCGEN05_LD_32X32B_X16(r, tmem_addr) \
    asm volatile( \
        "tcgen05.ld.sync.aligned.32x32b.x16.b32 " \
        "{%0, %1, %2, %3, %4, %5, %6, %7, " \
        " %8, %9, %10, %11, %12, %13, %14, %15}, [%16];" \
        : "=r"((r)[0]),  "=r"((r)[1]),  "=r"((r)[2]),  "=r"((r)[3]), \
          "=r"((r)[4]),  "=r"((r)[5]),  "=r"((r)[6]),  "=r"((r)[7]), \
          "=r"((r)[8]),  "=r"((r)[9]),  "=r"((r)[10]), "=r"((r)[11]), \
          "=r"((r)[12]), "=r"((r)[13]), "=r"((r)[14]), "=r"((r)[15]) \
        : "r"(tmem_addr))

__device__ __forceinline__ void mma_f16_ss(uint32_t d_tmem, uint64_t a_desc,
                                           uint64_t b_desc, uint32_t idesc,
                                           uint32_t enable) {
    asm volatile(
        "{\n\t"
        ".reg .pred p;\n\t"
        "setp.ne.u32 p, %5, 0;\n\t"
        "tcgen05.mma.cta_group::1.kind::f16 [%0], %1, %2, %3, {%4, %4, %4, %4}, p;\n\t"
        "}"
        :: "r"(d_tmem), "l"(a_desc), "l"(b_desc), "r"(idesc), "r"(0u), "r"(enable)
        : "memory");
}
#endif  // TC_OK

// K-major SW128 descriptor
__device__ __forceinline__ uint64_t desc_k_major(uint32_t addr) {
    return ((uint64_t)(addr >> 4) & 0x3FFF)
         | (1ull << 16) | (64ull << 32) | (1ull << 46) | (2ull << 61);
}

#define SW128(off) ((off) ^ (((off) >> 3) & 0x70))

#define IDESC_BF16_N128 0x8200490u
#define IDESC_BF16_N64  0x8100490u

// Fast pair split: hi = bf16-truncation (exact residual), lo = rn-bf16(x-hi).
__device__ __forceinline__ void bf16_split2(float v0, float v1,
                                            uint32_t& hp, uint32_t& lp) {
    uint32_t u0 = __float_as_uint(v0), u1 = __float_as_uint(v1);
    asm("prmt.b32 %0, %1, %2, 0x7632;" : "=r"(hp) : "r"(u0), "r"(u1));
    float l0 = v0 - __uint_as_float(u0 & 0xFFFF0000u);
    float l1 = v1 - __uint_as_float(u1 & 0xFFFF0000u);
    asm("cvt.rn.bf16x2.f32 %0, %1, %2;" : "=r"(lp) : "f"(l1), "f"(l0));
}

// ===========================================================================
// tcgen05 split-bf16 channel-mix GEMM (R15 proven, unchanged).
// ===========================================================================
#define TCG_SMEM_BYTES 66688

template <bool FUSE>
__global__ __launch_bounds__(256, 2) __cluster_dims__(1, 1, 1) void tc_gemm(
    const float* __restrict__ Wa, const float* __restrict__ Xa,
    const float* __restrict__ Wb, const float* __restrict__ Xb,
    const float* __restrict__ X2, float* __restrict__ OutA,
    float* __restrict__ OutB)
{
#if TC_OK
    extern __shared__ uint8_t dsm[];
    const uint32_t raw  = smem_to_u32(dsm);
    const uint32_t base = (raw + 1023u) & ~1023u;
    uint8_t* p = dsm + (base - raw);

    const uint32_t ctrl = base + 65536;
    const uint32_t mbar = ctrl + 8;

    const float* W; const float* X1; float* Out; int b;
    if (blockIdx.z < B_) { W = Wa; X1 = Xa; Out = OutA; b = blockIdx.z; }
    else                 { W = Wb; X1 = Xb; Out = OutB; b = blockIdx.z - B_; }

    const int row0 = blockIdx.y * 128;
    const int col0 = blockIdx.x * 128;
    const int tid  = threadIdx.x;
    const int wid  = tid >> 5;
    const int lid  = tid & 31;

    if (wid == 0) {
        TCGEN05_ALLOC(ctrl, 256);
        TCGEN05_RELINQUISH();
    }
    if (tid == 0) MBARRIER_INIT(mbar, 1);
    __syncthreads();
    uint32_t tmem;
    asm volatile("ld.shared.b32 %0, [%1];" : "=r"(tmem) : "r"(ctrl));

    const float* Wb_  = W + (size_t)row0 * U_;
    const float* X1b = X1 + (size_t)b * U_ * L_ + col0;
    const float* X2b = FUSE ? (X2 + (size_t)b * U_ * L_ + col0) : nullptr;

    float4 aR[8];
    float  bR[4][8];

    auto load_regs = [&](int c) {
        const int k0 = c * 64;
#pragma unroll
        for (int t = 0; t < 8; t++) {
            int idx = tid + t * 256;
            int m  = idx >> 4;
            int k4 = (idx & 15) << 2;
            aR[t] = *(const float4*)(Wb_ + (size_t)m * U_ + k0 + k4);
        }
#pragma unroll
        for (int ei = 0; ei < 4; ei++) {
            int n = lid + 32 * ei;
#pragma unroll
            for (int kk = 0; kk < 8; kk++) {
                size_t ro = (size_t)(k0 + wid * 8 + kk) * L_ + n;
                float v = X1b[ro];
                if (FUSE) v = 0.5f * (v + X2b[ro]);
                bR[ei][kk] = v;
            }
        }
    };

    auto store_stage = [&]() {
#pragma unroll
        for (int t = 0; t < 8; t++) {
            int idx = tid + t * 256;
            int m  = idx >> 4;
            int k4 = (idx & 15) << 2;
            float4 v = aR[t];
            uint32_t h0, l0, h1, l1;
            bf16_split2(v.x, v.y, h0, l0);
            bf16_split2(v.z, v.w, h1, l1);
            uint32_t off = (uint32_t)((m >> 3) * 1024 + (m & 7) * 128 + k4 * 2);
            uint32_t sw = SW128(off);
            *(uint2*)(p + sw)         = make_uint2(h0, h1);
            *(uint2*)(p + 16384 + sw) = make_uint2(l0, l1);
        }
#pragma unroll
        for (int ei = 0; ei < 4; ei++) {
            int n = lid + 32 * ei;
            uint32_t hp[4], lp[4];
#pragma unroll
            for (int kk = 0; kk < 4; kk++)
                bf16_split2(bR[ei][2 * kk], bR[ei][2 * kk + 1], hp[kk], lp[kk]);
            uint32_t off = (uint32_t)((n >> 3) * 1024 + (n & 7) * 128 + wid * 16);
            uint32_t sw = SW128(off);
            *(uint4*)(p + 32768 + sw) = make_uint4(hp[0], hp[1], hp[2], hp[3]);
            *(uint4*)(p + 49152 + sw) = make_uint4(lp[0], lp[1], lp[2], lp[3]);
        }
        FENCE_PROXY_ASYNC_SHARED_CTA();
    };

    load_regs(0);
    store_stage();
    __syncthreads();

    const int NC = U_ / 64;   // 8 chunks
    for (int c = 0; c < NC; c++) {
        if (wid == 0 && elect_one_pred()) {
            uint64_t ahi = desc_k_major(base);
            uint64_t alo = desc_k_major(base + 16384);
            uint64_t bhi = desc_k_major(base + 32768);
            uint64_t blo = desc_k_major(base + 49152);
#pragma unroll
            for (int s = 0; s < 4; s++) {
                uint64_t so = (uint64_t)(s * 2);
                mma_f16_ss(tmem, ahi + so, bhi + so, IDESC_BF16_N128,
                           (c == 0 && s == 0) ? 0u : 1u);
                mma_f16_ss(tmem, ahi + so, blo + so, IDESC_BF16_N128, 1u);
                mma_f16_ss(tmem, alo + so, bhi + so, IDESC_BF16_N128, 1u);
            }
            TCGEN05_COMMIT(mbar);
        }
        if (c + 1 < NC) load_regs(c + 1);
        MBARRIER_WAIT_PARITY(mbar, c & 1);
        if (c + 1 < NC) {
            store_stage();
            __syncthreads();
        }
    }

    TCGEN05_FENCE_AFTER();

    if (wid < 4) {
        const int m = wid * 32 + lid;
        float* op = Out + ((size_t)b * U_ + row0 + m) * L_ + col0;
#pragma unroll
        for (int j = 0; j < 4; j++) {
            uint32_t r32[32];
            TCGEN05_LD_32X32B_X32(r32, tmem + j * 32);
            TCGEN05_WAIT_LD();
            TCGEN05_FENCE_BEFORE();
#pragma unroll
            for (int q = 0; q < 8; q++) {
                float4 v = make_float4(__uint_as_float(r32[q * 4 + 0]),
                                       __uint_as_float(r32[q * 4 + 1]),
                                       __uint_as_float(r32[q * 4 + 2]),
                                       __uint_as_float(r32[q * 4 + 3]));
                *(float4*)(op + j * 32 + q * 4) = v;
            }
        }
    }
    __syncthreads();
    if (wid == 0) TCGEN05_DEALLOC(tmem, 256);
#else
    (void)Wa; (void)Xa; (void)Wb; (void)Xb; (void)X2; (void)OutA; (void)OutB;
#endif
}

// ===========================================================================
// tcgen05 attention — R15 + mask prefetched to 1-reg bitmask during the MMA
// window (R14's win without its x32-LDTM spill).
// smem: QHI 0 | QLO 16384 | KTHI 32768 | KTLO 40960 | KHI 49152 | KLO 57344
//       SHI 65536 | SLO 81920 | ctrl 98304 | cnts 98336
// ===========================================================================
#define AT_SMEM_BYTES 100384

__global__ __launch_bounds__(256, 2) __cluster_dims__(1, 1, 1) void attn_tc(
    const float* __restrict__ Q, const float* __restrict__ K,
    const int* __restrict__ mask, float* __restrict__ C)
{
#if TC_OK
    extern __shared__ uint8_t dsm[];
    const uint32_t raw  = smem_to_u32(dsm);
    const uint32_t base = (raw + 1023u) & ~1023u;
    uint8_t* p = dsm + (base - raw);

    const uint32_t QHI = base, QLO = base + 16384;
    const uint32_t KTHI = base + 32768, KTLO = base + 40960;
    const uint32_t KHI = base + 49152, KLO = base + 57344;
    const uint32_t SHI = base + 65536, SLO = base + 81920;
    const uint32_t ctrl = base + 98304;
    const uint32_t m1 = ctrl + 8;
    const uint32_t m2 = ctrl + 16;
    int* cnts = (int*)(p + 98336);

    const int b  = blockIdx.z;
    const int h  = blockIdx.x;
    const int x0 = blockIdx.y * 128;
    const int tid = threadIdx.x;
    const int wid = tid >> 5;
    const int lid = tid & 31;
    const int sub  = wid & 3;
    const int half = wid >> 2;

    if (wid == 0) {
        TCGEN05_ALLOC(ctrl, 256);
        TCGEN05_RELINQUISH();
    }
    if (tid == 0) { MBARRIER_INIT(m1, 1); MBARRIER_INIT(m2, 1); }
    __syncthreads();
    uint32_t tmem;
    asm volatile("ld.shared.b32 %0, [%1];" : "=r"(tmem) : "r"(ctrl));

    const float* Qb = Q + ((size_t)(b * U_ + h * D_)) * L_ + x0;
    const float* Kb = K + ((size_t)(b * U_ + h * D_)) * L_;
    const int*   Mb = mask + ((size_t)b * L_ + x0) * L_;

    const int x = sub * 32 + lid;

    // ---- stage Q^T [128x][64d] hi/lo (scale folded), once ----
#pragma unroll
    for (int ei = 0; ei < 4; ei++) {
        int xq = lid + 32 * ei;
        float rv[8];
#pragma unroll
        for (int kk = 0; kk < 8; kk++)
            rv[kk] = Qb[(size_t)(wid * 8 + kk) * L_ + xq] * SCALE_;
        uint32_t hp[4], lp[4];
#pragma unroll
        for (int kk = 0; kk < 4; kk++)
            bf16_split2(rv[2 * kk], rv[2 * kk + 1], hp[kk], lp[kk]);
        uint32_t sw = SW128((uint32_t)((xq >> 3) * 1024 + (xq & 7) * 128 + wid * 16));
        *(uint4*)(p + (QHI - base) + sw) = make_uint4(hp[0], hp[1], hp[2], hp[3]);
        *(uint4*)(p + (QLO - base) + sw) = make_uint4(lp[0], lp[1], lp[2], lp[3]);
    }

    float  ktR[2][8];
    float4 kR[4];

    auto load_kt_regs = [&](int y0n) {
#pragma unroll
        for (int ei = 0; ei < 2; ei++) {
            int y = lid + 32 * ei;
#pragma unroll
            for (int kk = 0; kk < 8; kk++)
                ktR[ei][kk] = Kb[(size_t)(wid * 8 + kk) * L_ + y0n + y];
        }
    };
    auto load_k_regs = [&](int y0n) {
#pragma unroll
        for (int t = 0; t < 4; t++) {
            int idx = tid + t * 256;
            int d  = idx >> 4;
            int y4 = (idx & 15) << 2;
            kR[t] = *(const float4*)(Kb + (size_t)d * L_ + y0n + y4);
        }
    };
    // mask bitmask for this thread's 32 y-columns of tile at y0n (1 reg)
    auto load_mask_bits = [&](int y0n) -> uint32_t {
        const int* mrow = Mb + (size_t)x * L_ + y0n + half * 32;
        uint32_t bits = 0;
#pragma unroll
        for (int t = 0; t < 8; t++) {
            int4 m = *(const int4*)(mrow + t * 4);
            bits |= (m.x != 0 ? 1u : 0u) << (t * 4 + 0);
            bits |= (m.y != 0 ? 1u : 0u) << (t * 4 + 1);
            bits |= (m.z != 0 ? 1u : 0u) << (t * 4 + 2);
            bits |= (m.w != 0 ? 1u : 0u) << (t * 4 + 3);
        }
        return bits;
    };
    auto store_kt = [&]() {
#pragma unroll
        for (int ei = 0; ei < 2; ei++) {
            int y = lid + 32 * ei;
            uint32_t hp[4], lp[4];
#pragma unroll
            for (int kk = 0; kk < 4; kk++)
                bf16_split2(ktR[ei][2 * kk], ktR[ei][2 * kk + 1], hp[kk], lp[kk]);
            uint32_t sw = SW128((uint32_t)((y >> 3) * 1024 + (y & 7) * 128 + wid * 16));
            *(uint4*)(p + (KTHI - base) + sw) = make_uint4(hp[0], hp[1], hp[2], hp[3]);
            *(uint4*)(p + (KTLO - base) + sw) = make_uint4(lp[0], lp[1], lp[2], lp[3]);
        }
    };
    auto store_k = [&]() {
#pragma unroll
        for (int t = 0; t < 4; t++) {
            int idx = tid + t * 256;
            int d  = idx >> 4;
            int y4 = (idx & 15) << 2;
            float4 v = kR[t];
            uint32_t h0, l0, h1, l1;
            bf16_split2(v.x, v.y, h0, l0);
            bf16_split2(v.z, v.w, h1, l1);
            uint32_t sw = SW128((uint32_t)((d >> 3) * 1024 + (d & 7) * 128 + y4 * 2));
            *(uint2*)(p + (KHI - base) + sw) = make_uint2(h0, h1);
            *(uint2*)(p + (KLO - base) + sw) = make_uint2(l0, l1);
        }
    };

    // prologue
    load_kt_regs(0);
    store_kt();
    FENCE_PROXY_ASYNC_SHARED_CTA();
    __syncthreads();
    if (wid == 0 && elect_one_pred()) {
        uint64_t ah = desc_k_major(QHI), al = desc_k_major(QLO);
        uint64_t bh = desc_k_major(KTHI), bl = desc_k_major(KTLO);
#pragma unroll
        for (int s = 0; s < 4; s++) {
            uint64_t so = (uint64_t)(s * 2);
            mma_f16_ss(tmem, ah + so, bh + so, IDESC_BF16_N64, s > 0 ? 1u : 0u);
            mma_f16_ss(tmem, ah + so, bl + so, IDESC_BF16_N64, 1u);
            mma_f16_ss(tmem, al + so, bh + so, IDESC_BF16_N64, 1u);
        }
        TCGEN05_COMMIT(m1);
    }
    uint32_t mbits = load_mask_bits(0);
    load_kt_regs(64);
    load_k_regs(0);

    int cnt = 0;

    for (int yt = 0; yt < 16; yt++) {
        MBARRIER_WAIT_PARITY(m1, yt & 1);
        TCGEN05_FENCE_AFTER();

        cnt += __popc(mbits);

        uint4 sh[2][2], sl[2][2];
#pragma unroll
        for (int h16 = 0; h16 < 2; h16++) {
            uint32_t s0[16];
            TCGEN05_LD_32X32B_X16(s0, tmem + half * 32 + h16 * 16);
            TCGEN05_WAIT_LD();
            TCGEN05_FENCE_BEFORE();
            float fv[16];
#pragma unroll
            for (int j = 0; j < 16; j++) {
                float v = __uint_as_float(s0[j]);
                v = v > 0.f ? v : 0.f;
                uint32_t mb = (mbits >> (h16 * 16 + j)) & 1u;
                fv[j] = mb ? v : 0.f;
            }
            uint32_t hp[8], lp[8];
#pragma unroll
            for (int j = 0; j < 8; j++)
                bf16_split2(fv[2 * j], fv[2 * j + 1], hp[j], lp[j]);
            sh[h16][0] = make_uint4(hp[0], hp[1], hp[2], hp[3]);
            sh[h16][1] = make_uint4(hp[4], hp[5], hp[6], hp[7]);
            sl[h16][0] = make_uint4(lp[0], lp[1], lp[2], lp[3]);
            sl[h16][1] = make_uint4(lp[4], lp[5], lp[6], lp[7]);
        }

        if (yt > 0) MBARRIER_WAIT_PARITY(m2, (yt - 1) & 1);

        {
            uint32_t off = (uint32_t)((x >> 3) * 1024 + (x & 7) * 128 + half * 64);
#pragma unroll
            for (int h16 = 0; h16 < 2; h16++)
#pragma unroll
                for (int g = 0; g < 2; g++) {
                    uint32_t sw = SW128(off + h16 * 32 + g * 16);
                    *(uint4*)(p + (SHI - base) + sw) = sh[h16][g];
                    *(uint4*)(p + (SLO - base) + sw) = sl[h16][g];
                }
        }
        store_k();
        if (yt + 1 < 16) store_kt();
        FENCE_PROXY_ASYNC_SHARED_CTA();
        __syncthreads();

        if (wid == 0 && elect_one_pred()) {
            {
                uint64_t ah = desc_k_major(SHI), al = desc_k_major(SLO);
                uint64_t bh = desc_k_major(KHI), bl = desc_k_major(KLO);
#pragma unroll
                for (int s = 0; s < 4; s++) {
                    uint64_t so = (uint64_t)(s * 2);
                    mma_f16_ss(tmem + 64, ah + so, bh + so, IDESC_BF16_N64,
                               (yt == 0 && s == 0) ? 0u : 1u);
                    mma_f16_ss(tmem + 64, ah + so, bl + so, IDESC_BF16_N64, 1u);
                    mma_f16_ss(tmem + 64, al + so, bh + so, IDESC_BF16_N64, 1u);
                }
                TCGEN05_COMMIT(m2);
            }
            if (yt + 1 < 16) {
                uint64_t ah = desc_k_major(QHI), al = desc_k_major(QLO);
                uint64_t bh = desc_k_major(KTHI), bl = desc_k_major(KTLO);
#pragma unroll
                for (int s = 0; s < 4; s++) {
                    uint64_t so = (uint64_t)(s * 2);
                    mma_f16_ss(tmem, ah + so, bh + so, IDESC_BF16_N64,
                               s > 0 ? 1u : 0u);
                    mma_f16_ss(tmem, ah + so, bl + so, IDESC_BF16_N64, 1u);
                    mma_f16_ss(tmem, al + so, bh + so, IDESC_BF16_N64, 1u);
                }
                TCGEN05_COMMIT(m1);
            }
        }

        // prefetch next mask/K/KT (overlaps both MMAs)
        if (yt + 1 < 16) {
            mbits = load_mask_bits((yt + 1) * 64);
            load_k_regs((yt + 1) * 64);
            if (yt + 2 < 16) load_kt_regs((yt + 2) * 64);
        }
    }

    MBARRIER_WAIT_PARITY(m2, 1);
    TCGEN05_FENCE_AFTER();

    {
        float* scr = (float*)p;
        __syncthreads();
        cnts[half * 128 + x] = cnt;
        __syncthreads();
        int tot = cnts[x] + cnts[128 + x];
        float inv = 1.0f / (float)(tot > 0 ? tot : 1);
#pragma unroll
        for (int h16 = 0; h16 < 2; h16++) {
            uint32_t c0[16];
            TCGEN05_LD_32X32B_X16(c0, tmem + 64 + half * 32 + h16 * 16);
            TCGEN05_WAIT_LD();
            TCGEN05_FENCE_BEFORE();
#pragma unroll
            for (int j = 0; j < 16; j++) {
                float v = __uint_as_float(c0[j]) * inv;
                scr[(half * 32 + h16 * 16 + j) * 132 + x] = v;
            }
        }
        __syncthreads();
        float* Cb = C + ((size_t)(b * U_ + h * D_)) * L_ + x0;
#pragma unroll 2
        for (int t = 0; t < 8; t++) {
            int idx = tid + t * 256;
            int d  = idx >> 5;
            int x4 = (idx & 31) << 2;
            float4 v = *(float4*)&scr[d * 132 + x4];
            *(float4*)(Cb + (size_t)d * L_ + x4) = v;
        }
    }
    __syncthreads();
    if (wid == 0) TCGEN05_DEALLOC(tmem, 256);
#else
    (void)Q; (void)K; (void)mask; (void)C;
#endif
}

// ---------------------------------------------------------------------------
extern "C" void kernel_launch(void* const* d_in, const int* in_sizes, int n_in,
                              void* d_out, int out_size)
{
    const float* x  = (const float*)d_in[0];
    const float* y  = (const float*)d_in[1];
    const int*   mk = (const int*)d_in[2];
    const float* wq = (const float*)d_in[3];
    const float* wk = (const float*)d_in[4];
    const float* wo = (const float*)d_in[5];
    float* out = (float*)d_out;

    float *Qp, *Kp, *Cp;
    cudaGetSymbolAddress((void**)&Qp, g_Q);
    cudaGetSymbolAddress((void**)&Kp, g_K);
    cudaGetSymbolAddress((void**)&Cp, g_C);

    cudaFuncSetAttribute(tc_gemm<false>, cudaFuncAttributeMaxDynamicSharedMemorySize,
                         TCG_SMEM_BYTES);
    cudaFuncSetAttribute(tc_gemm<true>, cudaFuncAttributeMaxDynamicSharedMemorySize,
                         TCG_SMEM_BYTES);
    cudaFuncSetAttribute(attn_tc, cudaFuncAttributeMaxDynamicSharedMemorySize,
                         AT_SMEM_BYTES);

    // fused Q+K projection: z in [0,16) -> Q=wq*x, z in [16,32) -> K=wk*y
    tc_gemm<false><<<dim3(L_ / 128, U_ / 128, 2 * B_), 256, TCG_SMEM_BYTES>>>(
        wq, x, wk, y, nullptr, Qp, Kp);
    attn_tc<<<dim3(H_, L_ / 128, B_), 256, AT_SMEM_BYTES>>>(Qp, Kp, mk, Cp);
    tc_gemm<true><<<dim3(L_ / 128, U_ / 128, B_), 256, TCG_SMEM_BYTES>>>(
        wo, Qp, nullptr, nullptr, Cp, out, nullptr);
}

// round 17
// speedup vs baseline: 1.6348x; 1.2884x over previous
#include <cuda_runtime.h>
#include <cuda_bf16.h>
#include <cstdint>
#include <cstddef>

// Problem constants
#define B_  16
#define U_  512
#define L_  1024
#define H_  8
#define D_  64
#define SCALE_ 0.125f   // 1/sqrt(64)

// Scratch (device globals — allocation-free rule).
__device__ __align__(256) float g_Q[(size_t)B_ * U_ * L_];
__device__ __align__(256) float g_K[(size_t)B_ * U_ * L_];
__device__ __align__(256) float g_C[(size_t)B_ * U_ * L_];

#if defined(__CUDA_ARCH_FEAT_SM103_ALL) || defined(__CUDA_ARCH_FEAT_SM100_ALL) || \
    defined(__CUDA_ARCH_FAMILY_SPECIFIC__) || defined(__CUDA_ARCH_SPECIFIC__)
#define TC_OK 1
#else
#define TC_OK 0
#endif

__device__ __forceinline__ uint32_t smem_to_u32(const void* p) {
    uint32_t a;
    asm("{ .reg .u64 t; cvta.to.shared.u64 t, %1; cvt.u32.u64 %0, t; }" : "=r"(a) : "l"(p));
    return a;
}
#define MBARRIER_INIT(mbar, count) \
    asm volatile("mbarrier.init.shared.b64 [%0], %1;" \
                 :: "r"((uint32_t)(mbar)), "r"((uint32_t)(count)) : "memory")
#define MBARRIER_WAIT_PARITY(mbar, parity) do {                                   \
    uint32_t _m = (uint32_t)(mbar); uint32_t _p = (uint32_t)(parity);             \
    asm volatile("{\n\t.reg .pred P1;\n\t"                                        \
        "WAIT_LOOP_%=:\n\t"                                                        \
        "mbarrier.try_wait.parity.acquire.cta.shared::cta.b64 P1, [%0], %1, 0x989680;\n\t" \
        "@P1 bra.uni WAIT_DONE_%=;\n\t"                                            \
        "bra.uni WAIT_LOOP_%=;\n\t"                                                \
        "WAIT_DONE_%=:\n\t}" :: "r"(_m), "r"(_p) : "memory");                      \
} while (0)
#define FENCE_PROXY_ASYNC_SHARED_CTA() asm volatile("fence.proxy.async.shared::cta;" ::: "memory")

#if TC_OK
__device__ __forceinline__ uint32_t elect_one_pred() {
    uint32_t pred;
    asm volatile("{\n\t.reg .pred p;\n\telect.sync _|p, 0xFFFFFFFF;\n\tselp.b32 %0, 1, 0, p;\n\t}"
                 : "=r"(pred));
    return pred;
}
#define TCGEN05_ALLOC(smem_result_addr, nCols) \
    asm volatile("tcgen05.alloc.cta_group::1.sync.aligned.shared::cta.b32 [%0], %1;" \
                 :: "r"((uint32_t)(smem_result_addr)), "r"((uint32_t)(nCols)) : "memory")
#define TCGEN05_DEALLOC(tmem_addr, nCols) \
    asm volatile("tcgen05.dealloc.cta_group::1.sync.aligned.b32 %0, %1;" \
                 :: "r"(tmem_addr), "r"((uint32_t)(nCols)))
#define TCGEN05_RELINQUISH() \
    asm volatile("tcgen05.relinquish_alloc_permit.cta_group::1.sync.aligned;")
#define TCGEN05_COMMIT(mbar) \
    asm volatile("tcgen05.commit.cta_group::1.mbarrier::arrive::one.shared::cluster.b64 [%0];" \
                 :: "r"((uint32_t)(mbar)) : "memory")
#define TCGEN05_FENCE_BEFORE() asm volatile("tcgen05.fence::before_thread_sync;" ::: "memory")
#define TCGEN05_FENCE_AFTER()  asm volatile("tcgen05.fence::after_thread_sync;"  ::: "memory")
#define TCGEN05_WAIT_LD()      asm volatile("tcgen05.wait::ld.sync.aligned;"     ::: "memory")
#define TCGEN05_LD_32X32B_X32(r, tmem_addr) \
    asm volatile( \
        "tcgen05.ld.sync.aligned.32x32b.x32.b32 " \
        "{%0, %1, %2, %3, %4, %5, %6, %7, " \
        " %8, %9, %10, %11, %12, %13, %14, %15, " \
        " %16, %17, %18, %19, %20, %21, %22, %23, " \
        " %24, %25, %26, %27, %28, %29, %30, %31}, [%32];" \
        : "=r"((r)[0]),  "=r"((r)[1]),  "=r"((r)[2]),  "=r"((r)[3]), \
          "=r"((r)[4]),  "=r"((r)[5]),  "=r"((r)[6]),  "=r"((r)[7]), \
          "=r"((r)[8]),  "=r"((r)[9]),  "=r"((r)[10]), "=r"((r)[11]), \
          "=r"((r)[12]), "=r"((r)[13]), "=r"((r)[14]), "=r"((r)[15]), \
          "=r"((r)[16]), "=r"((r)[17]), "=r"((r)[18]), "=r"((r)[19]), \
          "=r"((r)[20]), "=r"((r)[21]), "=r"((r)[22]), "=r"((r)[23]), \
          "=r"((r)[24]), "=r"((r)[25]), "=r"((r)[26]), "=r"((r)[27]), \
          "=r"((r)[28]), "=r"((r)[29]), "=r"((r)[30]), "=r"((r)[31]) \
        : "r"(tmem_addr))
#define TCGEN05_LD_32X32B_X16(r, tmem_addr) \
    asm volatile( \
        "tcgen05.ld.sync.aligned.32x32b.x16.b32 " \
        "{%0, %1, %2, %3, %4, %5, %6, %7, " \
        " %8, %9, %10, %11, %12, %13, %14, %15}, [%16];" \
        : "=r"((r)[0]),  "=r"((r)[1]),  "=r"((r)[2]),  "=r"((r)[3]), \
          "=r"((r)[4]),  "=r"((r)[5]),  "=r"((r)[6]),  "=r"((r)[7]), \
          "=r"((r)[8]),  "=r"((r)[9]),  "=r"((r)[10]), "=r"((r)[11]), \
          "=r"((r)[12]), "=r"((r)[13]), "=r"((r)[14]), "=r"((r)[15]) \
        : "r"(tmem_addr))

__device__ __forceinline__ void mma_f16_ss(uint32_t d_tmem, uint64_t a_desc,
                                           uint64_t b_desc, uint32_t idesc,
                                           uint32_t enable) {
    asm volatile(
        "{\n\t"
        ".reg .pred p;\n\t"
        "setp.ne.u32 p, %5, 0;\n\t"
        "tcgen05.mma.cta_group::1.kind::f16 [%0], %1, %2, %3, {%4, %4, %4, %4}, p;\n\t"
        "}"
        :: "r"(d_tmem), "l"(a_desc), "l"(b_desc), "r"(idesc), "r"(0u), "r"(enable)
        : "memory");
}
#endif  // TC_OK

__device__ __forceinline__ uint64_t desc_k_major(uint32_t addr) {
    return ((uint64_t)(addr >> 4) & 0x3FFF)
         | (1ull << 16) | (64ull << 32) | (1ull << 46) | (2ull << 61);
}

#define SW128(off) ((off) ^ (((off) >> 3) & 0x70))

#define IDESC_BF16_N128 0x8200490u
#define IDESC_BF16_N64  0x8100490u

__device__ __forceinline__ void bf16_split2(float v0, float v1,
                                            uint32_t& hp, uint32_t& lp) {
    uint32_t u0 = __float_as_uint(v0), u1 = __float_as_uint(v1);
    asm("prmt.b32 %0, %1, %2, 0x7632;" : "=r"(hp) : "r"(u0), "r"(u1));
    float l0 = v0 - __uint_as_float(u0 & 0xFFFF0000u);
    float l1 = v1 - __uint_as_float(u1 & 0xFFFF0000u);
    asm("cvt.rn.bf16x2.f32 %0, %1, %2;" : "=r"(lp) : "f"(l1), "f"(l0));
}

__device__ __forceinline__ uint32_t bf16_pack2(float v0, float v1) {
    uint32_t r;
    asm("cvt.rn.bf16x2.f32 %0, %1, %2;" : "=r"(r) : "f"(v1), "f"(v0));
    return r;
}

// ===========================================================================
// tcgen05 split-bf16 channel-mix GEMM (R15 proven, unchanged).
// ===========================================================================
#define TCG_SMEM_BYTES 66688

template <bool FUSE>
__global__ __launch_bounds__(256, 2) __cluster_dims__(1, 1, 1) void tc_gemm(
    const float* __restrict__ Wa, const float* __restrict__ Xa,
    const float* __restrict__ Wb, const float* __restrict__ Xb,
    const float* __restrict__ X2, float* __restrict__ OutA,
    float* __restrict__ OutB)
{
#if TC_OK
    extern __shared__ uint8_t dsm[];
    const uint32_t raw  = smem_to_u32(dsm);
    const uint32_t base = (raw + 1023u) & ~1023u;
    uint8_t* p = dsm + (base - raw);

    const uint32_t ctrl = base + 65536;
    const uint32_t mbar = ctrl + 8;

    const float* W; const float* X1; float* Out; int b;
    if (blockIdx.z < B_) { W = Wa; X1 = Xa; Out = OutA; b = blockIdx.z; }
    else                 { W = Wb; X1 = Xb; Out = OutB; b = blockIdx.z - B_; }

    const int row0 = blockIdx.y * 128;
    const int col0 = blockIdx.x * 128;
    const int tid  = threadIdx.x;
    const int wid  = tid >> 5;
    const int lid  = tid & 31;

    if (wid == 0) {
        TCGEN05_ALLOC(ctrl, 256);
        TCGEN05_RELINQUISH();
    }
    if (tid == 0) MBARRIER_INIT(mbar, 1);
    __syncthreads();
    uint32_t tmem;
    asm volatile("ld.shared.b32 %0, [%1];" : "=r"(tmem) : "r"(ctrl));

    const float* Wb_  = W + (size_t)row0 * U_;
    const float* X1b = X1 + (size_t)b * U_ * L_ + col0;
    const float* X2b = FUSE ? (X2 + (size_t)b * U_ * L_ + col0) : nullptr;

    float4 aR[8];
    float  bR[4][8];

    auto load_regs = [&](int c) {
        const int k0 = c * 64;
#pragma unroll
        for (int t = 0; t < 8; t++) {
            int idx = tid + t * 256;
            int m  = idx >> 4;
            int k4 = (idx & 15) << 2;
            aR[t] = *(const float4*)(Wb_ + (size_t)m * U_ + k0 + k4);
        }
#pragma unroll
        for (int ei = 0; ei < 4; ei++) {
            int n = lid + 32 * ei;
#pragma unroll
            for (int kk = 0; kk < 8; kk++) {
                size_t ro = (size_t)(k0 + wid * 8 + kk) * L_ + n;
                float v = X1b[ro];
                if (FUSE) v = 0.5f * (v + X2b[ro]);
                bR[ei][kk] = v;
            }
        }
    };

    auto store_stage = [&]() {
#pragma unroll
        for (int t = 0; t < 8; t++) {
            int idx = tid + t * 256;
            int m  = idx >> 4;
            int k4 = (idx & 15) << 2;
            float4 v = aR[t];
            uint32_t h0, l0, h1, l1;
            bf16_split2(v.x, v.y, h0, l0);
            bf16_split2(v.z, v.w, h1, l1);
            uint32_t off = (uint32_t)((m >> 3) * 1024 + (m & 7) * 128 + k4 * 2);
            uint32_t sw = SW128(off);
            *(uint2*)(p + sw)         = make_uint2(h0, h1);
            *(uint2*)(p + 16384 + sw) = make_uint2(l0, l1);
        }
#pragma unroll
        for (int ei = 0; ei < 4; ei++) {
            int n = lid + 32 * ei;
            uint32_t hp[4], lp[4];
#pragma unroll
            for (int kk = 0; kk < 4; kk++)
                bf16_split2(bR[ei][2 * kk], bR[ei][2 * kk + 1], hp[kk], lp[kk]);
            uint32_t off = (uint32_t)((n >> 3) * 1024 + (n & 7) * 128 + wid * 16);
            uint32_t sw = SW128(off);
            *(uint4*)(p + 32768 + sw) = make_uint4(hp[0], hp[1], hp[2], hp[3]);
            *(uint4*)(p + 49152 + sw) = make_uint4(lp[0], lp[1], lp[2], lp[3]);
        }
        FENCE_PROXY_ASYNC_SHARED_CTA();
    };

    load_regs(0);
    store_stage();
    __syncthreads();

    const int NC = U_ / 64;
    for (int c = 0; c < NC; c++) {
        if (wid == 0 && elect_one_pred()) {
            uint64_t ahi = desc_k_major(base);
            uint64_t alo = desc_k_major(base + 16384);
            uint64_t bhi = desc_k_major(base + 32768);
            uint64_t blo = desc_k_major(base + 49152);
#pragma unroll
            for (int s = 0; s < 4; s++) {
                uint64_t so = (uint64_t)(s * 2);
                mma_f16_ss(tmem, ahi + so, bhi + so, IDESC_BF16_N128,
                           (c == 0 && s == 0) ? 0u : 1u);
                mma_f16_ss(tmem, ahi + so, blo + so, IDESC_BF16_N128, 1u);
                mma_f16_ss(tmem, alo + so, bhi + so, IDESC_BF16_N128, 1u);
            }
            TCGEN05_COMMIT(mbar);
        }
        if (c + 1 < NC) load_regs(c + 1);
        MBARRIER_WAIT_PARITY(mbar, c & 1);
        if (c + 1 < NC) {
            store_stage();
            __syncthreads();
        }
    }

    TCGEN05_FENCE_AFTER();

    if (wid < 4) {
        const int m = wid * 32 + lid;
        float* op = Out + ((size_t)b * U_ + row0 + m) * L_ + col0;
#pragma unroll
        for (int j = 0; j < 4; j++) {
            uint32_t r32[32];
            TCGEN05_LD_32X32B_X32(r32, tmem + j * 32);
            TCGEN05_WAIT_LD();
            TCGEN05_FENCE_BEFORE();
#pragma unroll
            for (int q = 0; q < 8; q++) {
                float4 v = make_float4(__uint_as_float(r32[q * 4 + 0]),
                                       __uint_as_float(r32[q * 4 + 1]),
                                       __uint_as_float(r32[q * 4 + 2]),
                                       __uint_as_float(r32[q * 4 + 3]));
                *(float4*)(op + j * 32 + q * 4) = v;
            }
        }
    }
    __syncthreads();
    if (wid == 0) TCGEN05_DEALLOC(tmem, 256);
#else
    (void)Wa; (void)Xa; (void)Wb; (void)Xb; (void)X2; (void)OutA; (void)OutB;
#endif
}

// ===========================================================================
// tcgen05 attention — SINGLE-bf16 (errors diluted by n_el normalization):
// 8 MMAs/iter, half conversions, smem 49KB, occ 3, TMEM alloc 128 (S@0, C@64).
// ===========================================================================
#define AT_SMEM_BYTES 51456

__global__ __launch_bounds__(256, 3) __cluster_dims__(1, 1, 1) void attn_tc(
    const float* __restrict__ Q, const float* __restrict__ K,
    const int* __restrict__ mask, float* __restrict__ C)
{
#if TC_OK
    extern __shared__ uint8_t dsm[];
    const uint32_t raw  = smem_to_u32(dsm);
    const uint32_t base = (raw + 1023u) & ~1023u;
    uint8_t* p = dsm + (base - raw);

    const uint32_t QB  = base;
    const uint32_t KTB = base + 16384;
    const uint32_t KB  = base + 24576;
    const uint32_t SB  = base + 32768;
    const uint32_t ctrl = base + 49152;
    const uint32_t m1 = ctrl + 8;
    const uint32_t m2 = ctrl + 16;
    int* cnts = (int*)(p + 49184);

    const int b  = blockIdx.z;
    const int h  = blockIdx.x;
    const int x0 = blockIdx.y * 128;
    const int tid = threadIdx.x;
    const int wid = tid >> 5;
    const int lid = tid & 31;
    const int sub  = wid & 3;
    const int half = wid >> 2;

    if (wid == 0) {
        TCGEN05_ALLOC(ctrl, 128);
        TCGEN05_RELINQUISH();
    }
    if (tid == 0) { MBARRIER_INIT(m1, 1); MBARRIER_INIT(m2, 1); }
    __syncthreads();
    uint32_t tmem;
    asm volatile("ld.shared.b32 %0, [%1];" : "=r"(tmem) : "r"(ctrl));

    const float* Qb = Q + ((size_t)(b * U_ + h * D_)) * L_ + x0;
    const float* Kb = K + ((size_t)(b * U_ + h * D_)) * L_;
    const int*   Mb = mask + ((size_t)b * L_ + x0) * L_;

    const int x = sub * 32 + lid;

    // ---- stage Q [128x][64d] bf16 (scale folded), once ----
#pragma unroll
    for (int ei = 0; ei < 4; ei++) {
        int xq = lid + 32 * ei;
        float rv[8];
#pragma unroll
        for (int kk = 0; kk < 8; kk++)
            rv[kk] = Qb[(size_t)(wid * 8 + kk) * L_ + xq] * SCALE_;
        uint32_t pk[4];
#pragma unroll
        for (int kk = 0; kk < 4; kk++)
            pk[kk] = bf16_pack2(rv[2 * kk], rv[2 * kk + 1]);
        uint32_t sw = SW128((uint32_t)((xq >> 3) * 1024 + (xq & 7) * 128 + wid * 16));
        *(uint4*)(p + (QB - base) + sw) = make_uint4(pk[0], pk[1], pk[2], pk[3]);
    }

    float  ktR[2][8];
    float4 kR[4];

    auto load_kt_regs = [&](int y0n) {
#pragma unroll
        for (int ei = 0; ei < 2; ei++) {
            int y = lid + 32 * ei;
#pragma unroll
            for (int kk = 0; kk < 8; kk++)
                ktR[ei][kk] = Kb[(size_t)(wid * 8 + kk) * L_ + y0n + y];
        }
    };
    auto load_k_regs = [&](int y0n) {
#pragma unroll
        for (int t = 0; t < 4; t++) {
            int idx = tid + t * 256;
            int d  = idx >> 4;
            int y4 = (idx & 15) << 2;
            kR[t] = *(const float4*)(Kb + (size_t)d * L_ + y0n + y4);
        }
    };
    auto load_mask_bits = [&](int y0n) -> uint32_t {
        const int* mrow = Mb + (size_t)x * L_ + y0n + half * 32;
        uint32_t bits = 0;
#pragma unroll
        for (int t = 0; t < 8; t++) {
            int4 m = *(const int4*)(mrow + t * 4);
            bits |= (m.x != 0 ? 1u : 0u) << (t * 4 + 0);
            bits |= (m.y != 0 ? 1u : 0u) << (t * 4 + 1);
            bits |= (m.z != 0 ? 1u : 0u) << (t * 4 + 2);
            bits |= (m.w != 0 ? 1u : 0u) << (t * 4 + 3);
        }
        return bits;
    };
    auto store_kt = [&]() {
#pragma unroll
        for (int ei = 0; ei < 2; ei++) {
            int y = lid + 32 * ei;
            uint32_t pk[4];
#pragma unroll
            for (int kk = 0; kk < 4; kk++)
                pk[kk] = bf16_pack2(ktR[ei][2 * kk], ktR[ei][2 * kk + 1]);
            uint32_t sw = SW128((uint32_t)((y >> 3) * 1024 + (y & 7) * 128 + wid * 16));
            *(uint4*)(p + (KTB - base) + sw) = make_uint4(pk[0], pk[1], pk[2], pk[3]);
        }
    };
    auto store_k = [&]() {
#pragma unroll
        for (int t = 0; t < 4; t++) {
            int idx = tid + t * 256;
            int d  = idx >> 4;
            int y4 = (idx & 15) << 2;
            float4 v = kR[t];
            uint32_t p0 = bf16_pack2(v.x, v.y);
            uint32_t p1 = bf16_pack2(v.z, v.w);
            uint32_t sw = SW128((uint32_t)((d >> 3) * 1024 + (d & 7) * 128 + y4 * 2));
            *(uint2*)(p + (KB - base) + sw) = make_uint2(p0, p1);
        }
    };

    // prologue
    load_kt_regs(0);
    store_kt();
    FENCE_PROXY_ASYNC_SHARED_CTA();
    __syncthreads();
    if (wid == 0 && elect_one_pred()) {
        uint64_t ad = desc_k_major(QB), bd = desc_k_major(KTB);
#pragma unroll
        for (int s = 0; s < 4; s++)
            mma_f16_ss(tmem, ad + (uint64_t)(s * 2), bd + (uint64_t)(s * 2),
                       IDESC_BF16_N64, s > 0 ? 1u : 0u);
        TCGEN05_COMMIT(m1);
    }
    uint32_t mbits = load_mask_bits(0);
    load_kt_regs(64);
    load_k_regs(0);

    int cnt = 0;

    for (int yt = 0; yt < 16; yt++) {
        MBARRIER_WAIT_PARITY(m1, yt & 1);
        TCGEN05_FENCE_AFTER();

        cnt += __popc(mbits);

        uint4 sp[2][2];   // [half16][group] packed S' (bf16x2 x4)
#pragma unroll
        for (int h16 = 0; h16 < 2; h16++) {
            uint32_t s0[16];
            TCGEN05_LD_32X32B_X16(s0, tmem + half * 32 + h16 * 16);
            TCGEN05_WAIT_LD();
            TCGEN05_FENCE_BEFORE();
            float fv[16];
#pragma unroll
            for (int j = 0; j < 16; j++) {
                float v = __uint_as_float(s0[j]);
                v = v > 0.f ? v : 0.f;
                uint32_t mb = (mbits >> (h16 * 16 + j)) & 1u;
                fv[j] = mb ? v : 0.f;
            }
            uint32_t pk[8];
#pragma unroll
            for (int j = 0; j < 8; j++)
                pk[j] = bf16_pack2(fv[2 * j], fv[2 * j + 1]);
            sp[h16][0] = make_uint4(pk[0], pk[1], pk[2], pk[3]);
            sp[h16][1] = make_uint4(pk[4], pk[5], pk[6], pk[7]);
        }

        if (yt > 0) MBARRIER_WAIT_PARITY(m2, (yt - 1) & 1);

        {
            uint32_t off = (uint32_t)((x >> 3) * 1024 + (x & 7) * 128 + half * 64);
            *(uint4*)(p + (SB - base) + SW128(off))      = sp[0][0];
            *(uint4*)(p + (SB - base) + SW128(off + 16)) = sp[0][1];
            *(uint4*)(p + (SB - base) + SW128(off + 32)) = sp[1][0];
            *(uint4*)(p + (SB - base) + SW128(off + 48)) = sp[1][1];
        }
        store_k();
        if (yt + 1 < 16) store_kt();
        FENCE_PROXY_ASYNC_SHARED_CTA();
        __syncthreads();

        if (wid == 0 && elect_one_pred()) {
            {
                uint64_t ad = desc_k_major(SB), bd = desc_k_major(KB);
#pragma unroll
                for (int s = 0; s < 4; s++)
                    mma_f16_ss(tmem + 64, ad + (uint64_t)(s * 2),
                               bd + (uint64_t)(s * 2), IDESC_BF16_N64,
                               (yt == 0 && s == 0) ? 0u : 1u);
                TCGEN05_COMMIT(m2);
            }
            if (yt + 1 < 16) {
                uint64_t ad = desc_k_major(QB), bd = desc_k_major(KTB);
#pragma unroll
                for (int s = 0; s < 4; s++)
                    mma_f16_ss(tmem, ad + (uint64_t)(s * 2),
                               bd + (uint64_t)(s * 2), IDESC_BF16_N64,
                               s > 0 ? 1u : 0u);
                TCGEN05_COMMIT(m1);
            }
        }

        if (yt + 1 < 16) {
            mbits = load_mask_bits((yt + 1) * 64);
            load_k_regs((yt + 1) * 64);
            if (yt + 2 < 16) load_kt_regs((yt + 2) * 64);
        }
    }

    MBARRIER_WAIT_PARITY(m2, 1);
    TCGEN05_FENCE_AFTER();

    {
        float* scr = (float*)p;
        __syncthreads();
        cnts[half * 128 + x] = cnt;
        __syncthreads();
        int tot = cnts[x] + cnts[128 + x];
        float inv = 1.0f / (float)(tot > 0 ? tot : 1);
#pragma unroll
        for (int h16 = 0; h16 < 2; h16++) {
            uint32_t c0[16];
            TCGEN05_LD_32X32B_X16(c0, tmem + 64 + half * 32 + h16 * 16);
            TCGEN05_WAIT_LD();
            TCGEN05_FENCE_BEFORE();
#pragma unroll
            for (int j = 0; j < 16; j++) {
                float v = __uint_as_float(c0[j]) * inv;
                scr[(half * 32 + h16 * 16 + j) * 132 + x] = v;
            }
        }
        __syncthreads();
        float* Cb = C + ((size_t)(b * U_ + h * D_)) * L_ + x0;
#pragma unroll 2
        for (int t = 0; t < 8; t++) {
            int idx = tid + t * 256;
            int d  = idx >> 5;
            int x4 = (idx & 31) << 2;
            float4 v = *(float4*)&scr[d * 132 + x4];
            *(float4*)(Cb + (size_t)d * L_ + x4) = v;
        }
    }
    __syncthreads();
    if (wid == 0) TCGEN05_DEALLOC(tmem, 128);
#else
    (void)Q; (void)K; (void)mask; (void)C;
#endif
}

// ---------------------------------------------------------------------------
extern "C" void kernel_launch(void* const* d_in, const int* in_sizes, int n_in,
                              void* d_out, int out_size)
{
    const float* x  = (const float*)d_in[0];
    const float* y  = (const float*)d_in[1];
    const int*   mk = (const int*)d_in[2];
    const float* wq = (const float*)d_in[3];
    const float* wk = (const float*)d_in[4];
    const float* wo = (const float*)d_in[5];
    float* out = (float*)d_out;

    float *Qp, *Kp, *Cp;
    cudaGetSymbolAddress((void**)&Qp, g_Q);
    cudaGetSymbolAddress((void**)&Kp, g_K);
    cudaGetSymbolAddress((void**)&Cp, g_C);

    cudaFuncSetAttribute(tc_gemm<false>, cudaFuncAttributeMaxDynamicSharedMemorySize,
                         TCG_SMEM_BYTES);
    cudaFuncSetAttribute(tc_gemm<true>, cudaFuncAttributeMaxDynamicSharedMemorySize,
                         TCG_SMEM_BYTES);
    cudaFuncSetAttribute(attn_tc, cudaFuncAttributeMaxDynamicSharedMemorySize,
                         AT_SMEM_BYTES);

    // fused Q+K projection: z in [0,16) -> Q=wq*x, z in [16,32) -> K=wk*y
    tc_gemm<false><<<dim3(L_ / 128, U_ / 128, 2 * B_), 256, TCG_SMEM_BYTES>>>(
        wq, x, wk, y, nullptr, Qp, Kp);
    attn_tc<<<dim3(H_, L_ / 128, B_), 256, AT_SMEM_BYTES>>>(Qp, Kp, mk, Cp);
    tc_gemm<true><<<dim3(L_ / 128, U_ / 128, B_), 256, TCG_SMEM_BYTES>>>(
        wo, Qp, nullptr, nullptr, Cp, out, nullptr);
}